// round 1
// baseline (speedup 1.0000x reference)
#include <cuda_runtime.h>
#include <math.h>

#define BN_ 4096      // batch nodes
#define KN_ 32        // padded degree
#define DN_ 256       // latent dim
#define DH_ 128       // projection dim
#define INV_T 14.285714285714286f   // 1/0.07

// ---------------- scratch (device globals; no allocation) ----------------
__device__ float g_v1[BN_ * DN_];
__device__ float g_v2[BN_ * DN_];
__device__ float g_h [BN_ * DN_];
__device__ float g_z1[BN_ * DH_];
__device__ float g_z2[BN_ * DH_];
__device__ float g_rowsum[BN_];
__device__ float g_colsum[BN_];
__device__ float g_diag[BN_];
__device__ int   g_mask_u8;

// ---------------- mask dtype detection ----------------
// If mask is stored as int32, every 32-bit word is 0 or 1.
// If mask is stored as 1-byte bool, words are packed 0/1 bytes -> some word > 1.
__global__ void detect_mask_kernel(const unsigned int* __restrict__ m) {
    __shared__ int found;
    if (threadIdx.x == 0) found = 0;
    __syncthreads();
    for (int i = threadIdx.x; i < 4096; i += 256)
        if (m[i] > 1u) found = 1;
    __syncthreads();
    if (threadIdx.x == 0) g_mask_u8 = found;
}

__global__ void zero_kernel() {
    int i = blockIdx.x * 256 + threadIdx.x;
    if (i < BN_) { g_rowsum[i] = 0.f; g_colsum[i] = 0.f; }
}

// ---------------- aggregation (both views in one launch) ----------------
__global__ void aggregate_kernel(const float* __restrict__ nf,
                                 const float* __restrict__ rel,
                                 const int* __restrict__ nb1, const int* __restrict__ rl1, const void* __restrict__ m1,
                                 const int* __restrict__ nb2, const int* __restrict__ rl2, const void* __restrict__ m2,
                                 const int* __restrict__ selfids) {
    int b = blockIdx.x;
    const int* nb; const int* rl; const void* m; float* out;
    if (b < BN_) { nb = nb1; rl = rl1; m = m1; out = g_v1; }
    else         { b -= BN_; nb = nb2; rl = rl2; m = m2; out = g_v2; }

    __shared__ int s_nb[KN_], s_rl[KN_], s_m[KN_];
    __shared__ int s_cnt;
    int t = threadIdx.x;
    if (t < KN_) {   // exactly warp 0
        int mk;
        if (g_mask_u8) mk = ((const unsigned char*)m)[b * KN_ + t];
        else           mk = ((const int*)m)[b * KN_ + t];
        mk = (mk != 0);
        s_m[t]  = mk;
        s_nb[t] = nb[b * KN_ + t];
        s_rl[t] = rl[b * KN_ + t];
        unsigned bal = __ballot_sync(0xFFFFFFFFu, mk);
        if (t == 0) s_cnt = __popc(bal);
    }
    __syncthreads();
    int cnt = s_cnt;
    int d = t;  // 256 threads == DN_ dims
    float acc = 0.f;
#pragma unroll 4
    for (int k = 0; k < KN_; k++) {
        if (s_m[k])
            acc += nf[(size_t)s_nb[k] * DN_ + d] + rel[s_rl[k] * DN_ + d];
    }
    float res;
    if (cnt > 0) res = acc / (float)cnt;
    else         res = nf[(size_t)selfids[b] * DN_ + d];
    out[(size_t)b * DN_ + d] = res;
}

// ---------------- tiled fp32 GEMM: C = act(A[MxK] @ W[KxN] + bias) ----------------
template <bool RELU>
__global__ void gemm_proj_kernel(const float* __restrict__ A,
                                 const float* __restrict__ W,
                                 const float* __restrict__ bias,
                                 float* __restrict__ C,
                                 int M, int N, int K) {
    const int BM = 64, BNt = 64, BK = 16;
    __shared__ float As[BK][BM + 4];
    __shared__ float Bs[BK][BNt + 4];
    int tid = threadIdx.x;
    int tx = tid & 15, ty = tid >> 4;
    int bm = blockIdx.x * BM, bn = blockIdx.y * BNt;
    float c[4][4] = {};

    for (int k0 = 0; k0 < K; k0 += BK) {
        {   // A tile 64x16, transposed into smem
            int mrow = tid >> 2;
            int kk = (tid & 3) * 4;
            float4 v = *(const float4*)&A[(size_t)(bm + mrow) * K + k0 + kk];
            As[kk + 0][mrow] = v.x; As[kk + 1][mrow] = v.y;
            As[kk + 2][mrow] = v.z; As[kk + 3][mrow] = v.w;
        }
        {   // W tile 16x64, natural layout
            int kk = tid >> 4;
            int n  = (tid & 15) * 4;
            float4 v = *(const float4*)&W[(size_t)(k0 + kk) * N + bn + n];
            *(float4*)&Bs[kk][n] = v;
        }
        __syncthreads();
#pragma unroll
        for (int kk = 0; kk < BK; kk++) {
            float4 a4 = *(const float4*)&As[kk][ty * 4];
            float4 b4 = *(const float4*)&Bs[kk][tx * 4];
            float av[4] = {a4.x, a4.y, a4.z, a4.w};
            float bv[4] = {b4.x, b4.y, b4.z, b4.w};
#pragma unroll
            for (int i = 0; i < 4; i++)
#pragma unroll
                for (int j = 0; j < 4; j++)
                    c[i][j] = fmaf(av[i], bv[j], c[i][j]);
        }
        __syncthreads();
    }
#pragma unroll
    for (int i = 0; i < 4; i++) {
        int row = bm + ty * 4 + i;
#pragma unroll
        for (int j = 0; j < 4; j++) {
            int col = bn + tx * 4 + j;
            float v = c[i][j] + bias[col];
            if (RELU) v = fmaxf(v, 0.f);
            C[(size_t)row * N + col] = v;
        }
    }
}

// ---------------- row L2 normalization (z1 and z2 in one launch) ----------------
__global__ void normalize_kernel() {
    int r = blockIdx.x;
    float* z = (r < BN_) ? g_z1 : g_z2;
    int row = (r < BN_) ? r : (r - BN_);
    float v = z[(size_t)row * DH_ + threadIdx.x];
    float ss = v * v;
#pragma unroll
    for (int off = 16; off; off >>= 1) ss += __shfl_xor_sync(0xFFFFFFFFu, ss, off);
    __shared__ float w[4];
    if ((threadIdx.x & 31) == 0) w[threadIdx.x >> 5] = ss;
    __syncthreads();
    float tot = w[0] + w[1] + w[2] + w[3];
    z[(size_t)row * DH_ + threadIdx.x] = v / sqrtf(tot);
}

// ---------------- fused sim GEMM + shifted-exp LSE reduction ----------------
// sim[i,j] = dot(z1n[i], z2n[j]) * INV_T;  accumulate exp(sim - INV_T) into
// rowsum/colsum; write diag.
__global__ void sim_lse_kernel() {
    const int BM = 64, BNt = 64, BK = 16, K = DH_;
    __shared__ float As[BK][BM + 4];
    __shared__ float Bs[BK][BNt + 4];
    __shared__ float s_cs[BNt];
    int tid = threadIdx.x;
    int tx = tid & 15, ty = tid >> 4;
    int bm = blockIdx.x * BM, bn = blockIdx.y * BNt;
    if (tid < BNt) s_cs[tid] = 0.f;
    float c[4][4] = {};

    for (int k0 = 0; k0 < K; k0 += BK) {
        {
            int mrow = tid >> 2;
            int kk = (tid & 3) * 4;
            float4 v = *(const float4*)&g_z1[(size_t)(bm + mrow) * K + k0 + kk];
            As[kk + 0][mrow] = v.x; As[kk + 1][mrow] = v.y;
            As[kk + 2][mrow] = v.z; As[kk + 3][mrow] = v.w;
        }
        {
            int jrow = tid >> 2;
            int kk = (tid & 3) * 4;
            float4 v = *(const float4*)&g_z2[(size_t)(bn + jrow) * K + k0 + kk];
            Bs[kk + 0][jrow] = v.x; Bs[kk + 1][jrow] = v.y;
            Bs[kk + 2][jrow] = v.z; Bs[kk + 3][jrow] = v.w;
        }
        __syncthreads();
#pragma unroll
        for (int kk = 0; kk < BK; kk++) {
            float4 a4 = *(const float4*)&As[kk][ty * 4];
            float4 b4 = *(const float4*)&Bs[kk][tx * 4];
            float av[4] = {a4.x, a4.y, a4.z, a4.w};
            float bv[4] = {b4.x, b4.y, b4.z, b4.w};
#pragma unroll
            for (int i = 0; i < 4; i++)
#pragma unroll
                for (int j = 0; j < 4; j++)
                    c[i][j] = fmaf(av[i], bv[j], c[i][j]);
        }
        __syncthreads();
    }

    float rs[4] = {0.f, 0.f, 0.f, 0.f};
    float cs[4] = {0.f, 0.f, 0.f, 0.f};
    bool diag_tile = (bm == bn);
#pragma unroll
    for (int i = 0; i < 4; i++) {
        int ri = ty * 4 + i;
#pragma unroll
        for (int j = 0; j < 4; j++) {
            int cj = tx * 4 + j;
            float s = c[i][j] * INV_T;
            if (diag_tile && ri == cj) g_diag[bm + ri] = s;
            float ev = __expf(s - INV_T);   // shift: s <= INV_T always (cos <= 1)
            rs[i] += ev;
            cs[j] += ev;
        }
    }
    // row sums: reduce across 16 tx lanes (xor < 16 stays in half-warp)
#pragma unroll
    for (int i = 0; i < 4; i++) {
        float v = rs[i];
#pragma unroll
        for (int off = 8; off >= 1; off >>= 1) v += __shfl_xor_sync(0xFFFFFFFFu, v, off);
        if (tx == 0) atomicAdd(&g_rowsum[bm + ty * 4 + i], v);
    }
    // col sums: smem atomics then one global atomic per column
#pragma unroll
    for (int j = 0; j < 4; j++) atomicAdd(&s_cs[tx * 4 + j], cs[j]);
    __syncthreads();
    if (tid < BNt) atomicAdd(&g_colsum[bn + tid], s_cs[tid]);
}

// ---------------- final loss reduce ----------------
__global__ void loss_kernel(float* __restrict__ out) {
    float acc = 0.f;
    for (int i = threadIdx.x; i < BN_; i += 256) {
        acc += 0.5f * (logf(g_rowsum[i]) + logf(g_colsum[i])) + INV_T - g_diag[i];
    }
#pragma unroll
    for (int off = 16; off; off >>= 1) acc += __shfl_xor_sync(0xFFFFFFFFu, acc, off);
    __shared__ float w[8];
    if ((threadIdx.x & 31) == 0) w[threadIdx.x >> 5] = acc;
    __syncthreads();
    if (threadIdx.x == 0) {
        float tot = 0.f;
        for (int k = 0; k < 8; k++) tot += w[k];
        out[0] = tot / (float)BN_;
    }
}

// ---------------- launch ----------------
extern "C" void kernel_launch(void* const* d_in, const int* in_sizes, int n_in,
                              void* d_out, int out_size) {
    const float* nf   = (const float*)d_in[0];
    const float* rel  = (const float*)d_in[1];
    const int*   nb1  = (const int*)d_in[2];
    const int*   rl1  = (const int*)d_in[3];
    const void*  m1   = d_in[4];
    const int*   nb2  = (const int*)d_in[5];
    const int*   rl2  = (const int*)d_in[6];
    const void*  m2   = d_in[7];
    const int*   self_ = (const int*)d_in[8];
    const float* W1a  = (const float*)d_in[9];
    const float* b1a  = (const float*)d_in[10];
    const float* W1b  = (const float*)d_in[11];
    const float* b1b  = (const float*)d_in[12];
    const float* W2a  = (const float*)d_in[13];
    const float* b2a  = (const float*)d_in[14];
    const float* W2b  = (const float*)d_in[15];
    const float* b2b  = (const float*)d_in[16];

    float *p_v1, *p_v2, *p_h, *p_z1, *p_z2;
    cudaGetSymbolAddress((void**)&p_v1, g_v1);
    cudaGetSymbolAddress((void**)&p_v2, g_v2);
    cudaGetSymbolAddress((void**)&p_h,  g_h);
    cudaGetSymbolAddress((void**)&p_z1, g_z1);
    cudaGetSymbolAddress((void**)&p_z2, g_z2);

    detect_mask_kernel<<<1, 256>>>((const unsigned int*)m1);
    zero_kernel<<<16, 256>>>();
    aggregate_kernel<<<2 * BN_, 256>>>(nf, rel, nb1, rl1, m1, nb2, rl2, m2, self_);

    // view 1 projection
    gemm_proj_kernel<true ><<<dim3(BN_ / 64, DN_ / 64), 256>>>(p_v1, W1a, b1a, p_h,  BN_, DN_, DN_);
    gemm_proj_kernel<false><<<dim3(BN_ / 64, DH_ / 64), 256>>>(p_h,  W1b, b1b, p_z1, BN_, DH_, DN_);
    // view 2 projection (reuses g_h)
    gemm_proj_kernel<true ><<<dim3(BN_ / 64, DN_ / 64), 256>>>(p_v2, W2a, b2a, p_h,  BN_, DN_, DN_);
    gemm_proj_kernel<false><<<dim3(BN_ / 64, DH_ / 64), 256>>>(p_h,  W2b, b2b, p_z2, BN_, DH_, DN_);

    normalize_kernel<<<2 * BN_, 128>>>();
    sim_lse_kernel<<<dim3(BN_ / 64, BN_ / 64), 256>>>();
    loss_kernel<<<1, 256>>>((float*)d_out);
}

// round 2
// speedup vs baseline: 1.3208x; 1.3208x over previous
#include <cuda_runtime.h>
#include <cuda_bf16.h>
#include <math.h>

#define BN_ 4096
#define KN_ 32
#define DN_ 256
#define DH_ 128
#define INV_T 14.285714285714286f

typedef __nv_bfloat16 bf16;

// ---------------- scratch ----------------
__device__ __align__(16) bf16 g_v1h[BN_ * DN_];
__device__ __align__(16) bf16 g_v1l[BN_ * DN_];
__device__ __align__(16) bf16 g_v2h[BN_ * DN_];
__device__ __align__(16) bf16 g_v2l[BN_ * DN_];
__device__ __align__(16) bf16 g_hh [BN_ * DN_];
__device__ __align__(16) bf16 g_hl [BN_ * DN_];
__device__ __align__(16) float g_z1[BN_ * DH_];
__device__ __align__(16) float g_z2[BN_ * DH_];
__device__ __align__(16) bf16 g_z1h[BN_ * DH_];
__device__ __align__(16) bf16 g_z1l[BN_ * DH_];
__device__ __align__(16) bf16 g_z2h[BN_ * DH_];
__device__ __align__(16) bf16 g_z2l[BN_ * DH_];
__device__ __align__(16) bf16 g_w1ath[DN_ * DN_];
__device__ __align__(16) bf16 g_w1atl[DN_ * DN_];
__device__ __align__(16) bf16 g_w1bth[DH_ * DN_];
__device__ __align__(16) bf16 g_w1btl[DH_ * DN_];
__device__ __align__(16) bf16 g_w2ath[DN_ * DN_];
__device__ __align__(16) bf16 g_w2atl[DN_ * DN_];
__device__ __align__(16) bf16 g_w2bth[DH_ * DN_];
__device__ __align__(16) bf16 g_w2btl[DH_ * DN_];
__device__ float g_rowsum[BN_];
__device__ float g_colsum[BN_];
__device__ float g_diag[BN_];
__device__ int   g_mask_u8;

__device__ __forceinline__ void split_store(bf16* ph, bf16* pl, float v) {
    bf16 h = __float2bfloat16(v);
    *ph = h;
    *pl = __float2bfloat16(v - __bfloat162float(h));
}

// ---------------- mask dtype detection ----------------
__global__ void detect_mask_kernel(const unsigned int* __restrict__ m) {
    __shared__ int found;
    if (threadIdx.x == 0) found = 0;
    __syncthreads();
    for (int i = threadIdx.x; i < 4096; i += 256)
        if (m[i] > 1u) found = 1;
    __syncthreads();
    if (threadIdx.x == 0) g_mask_u8 = found;
}

__global__ void zero_kernel() {
    int i = blockIdx.x * 256 + threadIdx.x;
    if (i < BN_) { g_rowsum[i] = 0.f; g_colsum[i] = 0.f; }
}

// ---------------- aggregation (writes bf16 split directly) ----------------
__global__ void aggregate_kernel(const float* __restrict__ nf,
                                 const float* __restrict__ rel,
                                 const int* __restrict__ nb1, const int* __restrict__ rl1, const void* __restrict__ m1,
                                 const int* __restrict__ nb2, const int* __restrict__ rl2, const void* __restrict__ m2,
                                 const int* __restrict__ selfids) {
    int b = blockIdx.x;
    const int* nb; const int* rl; const void* m; bf16* oh; bf16* ol;
    if (b < BN_) { nb = nb1; rl = rl1; m = m1; oh = g_v1h; ol = g_v1l; }
    else         { b -= BN_; nb = nb2; rl = rl2; m = m2; oh = g_v2h; ol = g_v2l; }

    __shared__ int s_nb[KN_], s_rl[KN_], s_m[KN_];
    __shared__ int s_cnt;
    int t = threadIdx.x;
    if (t < KN_) {
        int mk;
        if (g_mask_u8) mk = ((const unsigned char*)m)[b * KN_ + t];
        else           mk = ((const int*)m)[b * KN_ + t];
        mk = (mk != 0);
        s_m[t]  = mk;
        s_nb[t] = nb[b * KN_ + t];
        s_rl[t] = rl[b * KN_ + t];
        unsigned bal = __ballot_sync(0xFFFFFFFFu, mk);
        if (t == 0) s_cnt = __popc(bal);
    }
    __syncthreads();
    int cnt = s_cnt;
    int d = t;
    float acc = 0.f;
#pragma unroll 4
    for (int k = 0; k < KN_; k++) {
        if (s_m[k])
            acc += nf[(size_t)s_nb[k] * DN_ + d] + rel[s_rl[k] * DN_ + d];
    }
    float res;
    if (cnt > 0) res = acc / (float)cnt;
    else         res = nf[(size_t)selfids[b] * DN_ + d];
    split_store(&oh[(size_t)b * DN_ + d], &ol[(size_t)b * DN_ + d], res);
}

// ---------------- weight split + transpose: W[K][N] -> Wt_hi/lo [N][K] ----------------
__global__ void wsplit_kernel(const float* __restrict__ W, bf16* __restrict__ Th,
                              bf16* __restrict__ Tl, int K, int N) {
    int idx = blockIdx.x * 256 + threadIdx.x;
    if (idx >= K * N) return;
    int k = idx / N, n = idx % N;
    split_store(&Th[(size_t)n * K + k], &Tl[(size_t)n * K + k], W[idx]);
}

// ---------------- mma helpers ----------------
__device__ __forceinline__ void mma16816(float c[4], unsigned a0, unsigned a1, unsigned a2, unsigned a3,
                                         unsigned b0, unsigned b1) {
    asm volatile("mma.sync.aligned.m16n8k16.row.col.f32.bf16.bf16.f32 "
                 "{%0,%1,%2,%3}, {%4,%5,%6,%7}, {%8,%9}, {%0,%1,%2,%3};\n"
                 : "+f"(c[0]), "+f"(c[1]), "+f"(c[2]), "+f"(c[3])
                 : "r"(a0), "r"(a1), "r"(a2), "r"(a3), "r"(b0), "r"(b1));
}

#define TS 40   // smem tile stride in bf16 (32 + 8 pad, conflict-friendly, 16B aligned)

// load 128x32 bf16 tile from G (leading dim ld) rows [row0,row0+128), cols [k0,k0+32)
__device__ __forceinline__ void load_tile(bf16* S, const bf16* G, int row0, int ld, int k0, int tid) {
#pragma unroll
    for (int i = 0; i < 2; i++) {
        int e = tid + i * 256;
        int row = e >> 2, seg = e & 3;
        *(uint4*)(S + row * TS + seg * 8) =
            *(const uint4*)(G + (size_t)(row0 + row) * ld + k0 + seg * 8);
    }
}

// fragment loads (lane decomposition: grp = lane>>2, qp = (lane&3)*2)
__device__ __forceinline__ void ldfragA(unsigned a[4], const bf16* S, int rb, int kk, int grp, int qp) {
    a[0] = *(const unsigned*)(S + (rb + grp) * TS + kk + qp);
    a[1] = *(const unsigned*)(S + (rb + grp + 8) * TS + kk + qp);
    a[2] = *(const unsigned*)(S + (rb + grp) * TS + kk + 8 + qp);
    a[3] = *(const unsigned*)(S + (rb + grp + 8) * TS + kk + 8 + qp);
}
__device__ __forceinline__ void ldfragB(unsigned b[2], const bf16* S, int nb, int kk, int grp, int qp) {
    b[0] = *(const unsigned*)(S + (nb + grp) * TS + kk + qp);
    b[1] = *(const unsigned*)(S + (nb + grp) * TS + kk + 8 + qp);
}

// ---------------- split-bf16 MMA projection: C = act(A @ Wt^T + bias) ----------------
// OUTMODE 0: relu + write bf16 split (Ch, Cl).  OUTMODE 1: write fp32 Cf (no relu).
template <int OUTMODE>
__global__ void __launch_bounds__(256) mma_proj_kernel(
        const bf16* __restrict__ Ah, const bf16* __restrict__ Al,
        const bf16* __restrict__ Bh, const bf16* __restrict__ Bl,
        const float* __restrict__ bias,
        float* __restrict__ Cf, bf16* __restrict__ Ch, bf16* __restrict__ Cl,
        int N, int K) {
    __shared__ __align__(16) bf16 sAh[128 * TS], sAl[128 * TS], sBh[128 * TS], sBl[128 * TS];
    int tid = threadIdx.x;
    int lane = tid & 31, w = tid >> 5;
    int wr = w >> 2, wc = w & 3;
    int grp = lane >> 2, qp = (lane & 3) * 2;
    int bm = blockIdx.x * 128, bn = blockIdx.y * 128;

    float c[4][4][4] = {};

    for (int k0 = 0; k0 < K; k0 += 32) {
        load_tile(sAh, Ah, bm, K, k0, tid);
        load_tile(sAl, Al, bm, K, k0, tid);
        load_tile(sBh, Bh, bn, K, k0, tid);
        load_tile(sBl, Bl, bn, K, k0, tid);
        __syncthreads();
#pragma unroll
        for (int kk = 0; kk < 32; kk += 16) {
            unsigned ah[4][4], bh[4][2];
#pragma unroll
            for (int ms = 0; ms < 4; ms++) ldfragA(ah[ms], sAh, wr * 64 + ms * 16, kk, grp, qp);
#pragma unroll
            for (int ns = 0; ns < 4; ns++) ldfragB(bh[ns], sBh, wc * 32 + ns * 8, kk, grp, qp);
#pragma unroll
            for (int ms = 0; ms < 4; ms++)
#pragma unroll
                for (int ns = 0; ns < 4; ns++)
                    mma16816(c[ms][ns], ah[ms][0], ah[ms][1], ah[ms][2], ah[ms][3], bh[ns][0], bh[ns][1]);
            {   // Ah * Bl
                unsigned bl[4][2];
#pragma unroll
                for (int ns = 0; ns < 4; ns++) ldfragB(bl[ns], sBl, wc * 32 + ns * 8, kk, grp, qp);
#pragma unroll
                for (int ms = 0; ms < 4; ms++)
#pragma unroll
                    for (int ns = 0; ns < 4; ns++)
                        mma16816(c[ms][ns], ah[ms][0], ah[ms][1], ah[ms][2], ah[ms][3], bl[ns][0], bl[ns][1]);
            }
            {   // Al * Bh
                unsigned al[4][4];
#pragma unroll
                for (int ms = 0; ms < 4; ms++) ldfragA(al[ms], sAl, wr * 64 + ms * 16, kk, grp, qp);
#pragma unroll
                for (int ms = 0; ms < 4; ms++)
#pragma unroll
                    for (int ns = 0; ns < 4; ns++)
                        mma16816(c[ms][ns], al[ms][0], al[ms][1], al[ms][2], al[ms][3], bh[ns][0], bh[ns][1]);
            }
        }
        __syncthreads();
    }

#pragma unroll
    for (int ms = 0; ms < 4; ms++) {
#pragma unroll
        for (int ns = 0; ns < 4; ns++) {
            int col = bn + wc * 32 + ns * 8 + qp;
            float b0 = bias[col], b1 = bias[col + 1];
#pragma unroll
            for (int h = 0; h < 2; h++) {
                int row = bm + wr * 64 + ms * 16 + grp + 8 * h;
                float v0 = c[ms][ns][2 * h + 0] + b0;
                float v1 = c[ms][ns][2 * h + 1] + b1;
                if (OUTMODE == 0) {
                    v0 = fmaxf(v0, 0.f); v1 = fmaxf(v1, 0.f);
                    bf16 h0 = __float2bfloat16(v0), h1 = __float2bfloat16(v1);
                    bf16 l0 = __float2bfloat16(v0 - __bfloat162float(h0));
                    bf16 l1 = __float2bfloat16(v1 - __bfloat162float(h1));
                    __nv_bfloat162 hp; hp.x = h0; hp.y = h1;
                    __nv_bfloat162 lp; lp.x = l0; lp.y = l1;
                    *(__nv_bfloat162*)(Ch + (size_t)row * N + col) = hp;
                    *(__nv_bfloat162*)(Cl + (size_t)row * N + col) = lp;
                } else {
                    float2 o; o.x = v0; o.y = v1;
                    *(float2*)(Cf + (size_t)row * N + col) = o;
                }
            }
        }
    }
}

// ---------------- normalize + split ----------------
__global__ void normalize_kernel() {
    int r = blockIdx.x;
    bool view2 = r >= BN_;
    int row = view2 ? r - BN_ : r;
    const float* z = view2 ? g_z2 : g_z1;
    bf16* zh = view2 ? g_z2h : g_z1h;
    bf16* zl = view2 ? g_z2l : g_z1l;
    float v = z[(size_t)row * DH_ + threadIdx.x];
    float ss = v * v;
#pragma unroll
    for (int off = 16; off; off >>= 1) ss += __shfl_xor_sync(0xFFFFFFFFu, ss, off);
    __shared__ float wsum[4];
    if ((threadIdx.x & 31) == 0) wsum[threadIdx.x >> 5] = ss;
    __syncthreads();
    float tot = wsum[0] + wsum[1] + wsum[2] + wsum[3];
    float s = v / sqrtf(tot);
    split_store(&zh[(size_t)row * DH_ + threadIdx.x], &zl[(size_t)row * DH_ + threadIdx.x], s);
}

// ---------------- fused split-bf16 sim GEMM + shifted-exp LSE ----------------
__global__ void __launch_bounds__(256) sim_lse_kernel() {
    __shared__ __align__(16) bf16 sAh[128 * TS], sAl[128 * TS], sBh[128 * TS], sBl[128 * TS];
    __shared__ float s_rs[128], s_cs[128];
    int tid = threadIdx.x;
    int lane = tid & 31, w = tid >> 5;
    int wr = w >> 2, wc = w & 3;
    int grp = lane >> 2, qp = (lane & 3) * 2;
    int bm = blockIdx.x * 128, bn = blockIdx.y * 128;
    if (tid < 128) { s_rs[tid] = 0.f; s_cs[tid] = 0.f; }

    float c[4][4][4] = {};

    for (int k0 = 0; k0 < DH_; k0 += 32) {
        load_tile(sAh, g_z1h, bm, DH_, k0, tid);
        load_tile(sAl, g_z1l, bm, DH_, k0, tid);
        load_tile(sBh, g_z2h, bn, DH_, k0, tid);
        load_tile(sBl, g_z2l, bn, DH_, k0, tid);
        __syncthreads();
#pragma unroll
        for (int kk = 0; kk < 32; kk += 16) {
            unsigned ah[4][4], bh[4][2];
#pragma unroll
            for (int ms = 0; ms < 4; ms++) ldfragA(ah[ms], sAh, wr * 64 + ms * 16, kk, grp, qp);
#pragma unroll
            for (int ns = 0; ns < 4; ns++) ldfragB(bh[ns], sBh, wc * 32 + ns * 8, kk, grp, qp);
#pragma unroll
            for (int ms = 0; ms < 4; ms++)
#pragma unroll
                for (int ns = 0; ns < 4; ns++)
                    mma16816(c[ms][ns], ah[ms][0], ah[ms][1], ah[ms][2], ah[ms][3], bh[ns][0], bh[ns][1]);
            {
                unsigned bl[4][2];
#pragma unroll
                for (int ns = 0; ns < 4; ns++) ldfragB(bl[ns], sBl, wc * 32 + ns * 8, kk, grp, qp);
#pragma unroll
                for (int ms = 0; ms < 4; ms++)
#pragma unroll
                    for (int ns = 0; ns < 4; ns++)
                        mma16816(c[ms][ns], ah[ms][0], ah[ms][1], ah[ms][2], ah[ms][3], bl[ns][0], bl[ns][1]);
            }
            {
                unsigned al[4][4];
#pragma unroll
                for (int ms = 0; ms < 4; ms++) ldfragA(al[ms], sAl, wr * 64 + ms * 16, kk, grp, qp);
#pragma unroll
                for (int ms = 0; ms < 4; ms++)
#pragma unroll
                    for (int ns = 0; ns < 4; ns++)
                        mma16816(c[ms][ns], al[ms][0], al[ms][1], al[ms][2], al[ms][3], bh[ns][0], bh[ns][1]);
            }
        }
        __syncthreads();
    }

    float rs[4][2] = {}, cs[4][2] = {};
#pragma unroll
    for (int ms = 0; ms < 4; ms++) {
#pragma unroll
        for (int ns = 0; ns < 4; ns++) {
#pragma unroll
            for (int r = 0; r < 4; r++) {
                int h = r >> 1, p = r & 1;
                int row = bm + wr * 64 + ms * 16 + grp + 8 * h;
                int col = bn + wc * 32 + ns * 8 + qp + p;
                float s = c[ms][ns][r] * INV_T;
                if (row == col) g_diag[row] = s;
                float ev = __expf(s - INV_T);
                rs[ms][h] += ev;
                cs[ns][p] += ev;
            }
        }
    }
    // row sums: reduce over lane&3
#pragma unroll
    for (int ms = 0; ms < 4; ms++)
#pragma unroll
        for (int h = 0; h < 2; h++) {
            float v = rs[ms][h];
            v += __shfl_xor_sync(0xFFFFFFFFu, v, 1);
            v += __shfl_xor_sync(0xFFFFFFFFu, v, 2);
            if ((lane & 3) == 0)
                atomicAdd(&s_rs[wr * 64 + ms * 16 + grp + 8 * h], v);
        }
    // col sums: reduce over lane>>2
#pragma unroll
    for (int ns = 0; ns < 4; ns++)
#pragma unroll
        for (int p = 0; p < 2; p++) {
            float v = cs[ns][p];
            v += __shfl_xor_sync(0xFFFFFFFFu, v, 4);
            v += __shfl_xor_sync(0xFFFFFFFFu, v, 8);
            v += __shfl_xor_sync(0xFFFFFFFFu, v, 16);
            if (grp == 0)
                atomicAdd(&s_cs[wc * 32 + ns * 8 + qp + p], v);
        }
    __syncthreads();
    if (tid < 128) {
        atomicAdd(&g_rowsum[bm + tid], s_rs[tid]);
        atomicAdd(&g_colsum[bn + tid], s_cs[tid]);
    }
}

// ---------------- final loss reduce ----------------
__global__ void loss_kernel(float* __restrict__ out) {
    float acc = 0.f;
    for (int i = threadIdx.x; i < BN_; i += 256) {
        acc += 0.5f * (logf(g_rowsum[i]) + logf(g_colsum[i])) + INV_T - g_diag[i];
    }
#pragma unroll
    for (int off = 16; off; off >>= 1) acc += __shfl_xor_sync(0xFFFFFFFFu, acc, off);
    __shared__ float wsum[8];
    if ((threadIdx.x & 31) == 0) wsum[threadIdx.x >> 5] = acc;
    __syncthreads();
    if (threadIdx.x == 0) {
        float tot = 0.f;
        for (int k = 0; k < 8; k++) tot += wsum[k];
        out[0] = tot / (float)BN_;
    }
}

// ---------------- launch ----------------
extern "C" void kernel_launch(void* const* d_in, const int* in_sizes, int n_in,
                              void* d_out, int out_size) {
    const float* nf   = (const float*)d_in[0];
    const float* rel  = (const float*)d_in[1];
    const int*   nb1  = (const int*)d_in[2];
    const int*   rl1  = (const int*)d_in[3];
    const void*  m1   = d_in[4];
    const int*   nb2  = (const int*)d_in[5];
    const int*   rl2  = (const int*)d_in[6];
    const void*  m2   = d_in[7];
    const int*   self_ = (const int*)d_in[8];
    const float* W1a  = (const float*)d_in[9];
    const float* b1a  = (const float*)d_in[10];
    const float* W1b  = (const float*)d_in[11];
    const float* b1b  = (const float*)d_in[12];
    const float* W2a  = (const float*)d_in[13];
    const float* b2a  = (const float*)d_in[14];
    const float* W2b  = (const float*)d_in[15];
    const float* b2b  = (const float*)d_in[16];

    bf16 *p_v1h, *p_v1l, *p_v2h, *p_v2l, *p_hh, *p_hl;
    bf16 *p_w1ath, *p_w1atl, *p_w1bth, *p_w1btl, *p_w2ath, *p_w2atl, *p_w2bth, *p_w2btl;
    float *p_z1, *p_z2;
    cudaGetSymbolAddress((void**)&p_v1h, g_v1h);
    cudaGetSymbolAddress((void**)&p_v1l, g_v1l);
    cudaGetSymbolAddress((void**)&p_v2h, g_v2h);
    cudaGetSymbolAddress((void**)&p_v2l, g_v2l);
    cudaGetSymbolAddress((void**)&p_hh,  g_hh);
    cudaGetSymbolAddress((void**)&p_hl,  g_hl);
    cudaGetSymbolAddress((void**)&p_z1,  g_z1);
    cudaGetSymbolAddress((void**)&p_z2,  g_z2);
    cudaGetSymbolAddress((void**)&p_w1ath, g_w1ath);
    cudaGetSymbolAddress((void**)&p_w1atl, g_w1atl);
    cudaGetSymbolAddress((void**)&p_w1bth, g_w1bth);
    cudaGetSymbolAddress((void**)&p_w1btl, g_w1btl);
    cudaGetSymbolAddress((void**)&p_w2ath, g_w2ath);
    cudaGetSymbolAddress((void**)&p_w2atl, g_w2atl);
    cudaGetSymbolAddress((void**)&p_w2bth, g_w2bth);
    cudaGetSymbolAddress((void**)&p_w2btl, g_w2btl);

    detect_mask_kernel<<<1, 256>>>((const unsigned int*)m1);
    zero_kernel<<<16, 256>>>();
    aggregate_kernel<<<2 * BN_, 256>>>(nf, rel, nb1, rl1, m1, nb2, rl2, m2, self_);

    wsplit_kernel<<<(DN_ * DN_ + 255) / 256, 256>>>(W1a, p_w1ath, p_w1atl, DN_, DN_);
    wsplit_kernel<<<(DN_ * DH_ + 255) / 256, 256>>>(W1b, p_w1bth, p_w1btl, DN_, DH_);
    wsplit_kernel<<<(DN_ * DN_ + 255) / 256, 256>>>(W2a, p_w2ath, p_w2atl, DN_, DN_);
    wsplit_kernel<<<(DN_ * DH_ + 255) / 256, 256>>>(W2b, p_w2bth, p_w2btl, DN_, DH_);

    // view 1
    mma_proj_kernel<0><<<dim3(BN_ / 128, DN_ / 128), 256>>>(p_v1h, p_v1l, p_w1ath, p_w1atl, b1a,
                                                            nullptr, p_hh, p_hl, DN_, DN_);
    mma_proj_kernel<1><<<dim3(BN_ / 128, DH_ / 128), 256>>>(p_hh, p_hl, p_w1bth, p_w1btl, b1b,
                                                            p_z1, nullptr, nullptr, DH_, DN_);
    // view 2
    mma_proj_kernel<0><<<dim3(BN_ / 128, DN_ / 128), 256>>>(p_v2h, p_v2l, p_w2ath, p_w2atl, b2a,
                                                            nullptr, p_hh, p_hl, DN_, DN_);
    mma_proj_kernel<1><<<dim3(BN_ / 128, DH_ / 128), 256>>>(p_hh, p_hl, p_w2bth, p_w2btl, b2b,
                                                            p_z2, nullptr, nullptr, DH_, DN_);

    normalize_kernel<<<2 * BN_, 128>>>();
    sim_lse_kernel<<<dim3(BN_ / 128, BN_ / 128), 256>>>();
    loss_kernel<<<1, 256>>>((float*)d_out);
}

// round 7
// speedup vs baseline: 1.6510x; 1.2500x over previous
#include <cuda_runtime.h>
#include <cuda_bf16.h>
#include <math.h>

#define BN_ 4096
#define KN_ 32
#define DN_ 256
#define DH_ 128
#define INV_T 14.285714285714286f

typedef __nv_bfloat16 bf16;

// ---------------- scratch ----------------
__device__ __align__(16) bf16 g_v1h[BN_ * DN_];
__device__ __align__(16) bf16 g_v1l[BN_ * DN_];
__device__ __align__(16) bf16 g_v2h[BN_ * DN_];
__device__ __align__(16) bf16 g_v2l[BN_ * DN_];
__device__ __align__(16) bf16 g_h1h[BN_ * DN_];
__device__ __align__(16) bf16 g_h1l[BN_ * DN_];
__device__ __align__(16) bf16 g_h2h[BN_ * DN_];
__device__ __align__(16) bf16 g_h2l[BN_ * DN_];
__device__ __align__(16) bf16 g_z1h[BN_ * DH_];
__device__ __align__(16) bf16 g_z1l[BN_ * DH_];
__device__ __align__(16) bf16 g_z2h[BN_ * DH_];
__device__ __align__(16) bf16 g_z2l[BN_ * DH_];
__device__ __align__(16) bf16 g_w1ath[DN_ * DN_];
__device__ __align__(16) bf16 g_w1atl[DN_ * DN_];
__device__ __align__(16) bf16 g_w1bth[DH_ * DN_];
__device__ __align__(16) bf16 g_w1btl[DH_ * DN_];
__device__ __align__(16) bf16 g_w2ath[DN_ * DN_];
__device__ __align__(16) bf16 g_w2atl[DN_ * DN_];
__device__ __align__(16) bf16 g_w2bth[DH_ * DN_];
__device__ __align__(16) bf16 g_w2btl[DH_ * DN_];
__device__ float g_rowsum[BN_];
__device__ float g_colsum[BN_];
__device__ float g_diag[BN_];
__device__ int   g_mask_u8;

__device__ __forceinline__ void split_store(bf16* ph, bf16* pl, float v) {
    bf16 h = __float2bfloat16(v);
    *ph = h;
    *pl = __float2bfloat16(v - __bfloat162float(h));
}

// ---------------- mask dtype detection ----------------
__global__ void detect_mask_kernel(const unsigned int* __restrict__ m) {
    __shared__ int found;
    if (threadIdx.x == 0) found = 0;
    __syncthreads();
    for (int i = threadIdx.x; i < 4096; i += 256)
        if (m[i] > 1u) found = 1;
    __syncthreads();
    if (threadIdx.x == 0) g_mask_u8 = found;
}

// ---------------- fused prep: zero accumulators + split/transpose all weights ----------------
__global__ void prep_kernel(const float* __restrict__ W1a, const float* __restrict__ W1b,
                            const float* __restrict__ W2a, const float* __restrict__ W2b) {
    int idx = blockIdx.x * 256 + threadIdx.x;
    if (idx < BN_) { g_rowsum[idx] = 0.f; g_colsum[idx] = 0.f; }
    int i = idx;
    const float* W; bf16* Th; bf16* Tl; int K, N;
    if (i < DN_ * DN_)                   { W = W1a; Th = g_w1ath; Tl = g_w1atl; K = DN_; N = DN_; }
    else if ((i -= DN_ * DN_) < DN_ * DH_) { W = W1b; Th = g_w1bth; Tl = g_w1btl; K = DN_; N = DH_; }
    else if ((i -= DN_ * DH_) < DN_ * DN_) { W = W2a; Th = g_w2ath; Tl = g_w2atl; K = DN_; N = DN_; }
    else if ((i -= DN_ * DN_) < DN_ * DH_) { W = W2b; Th = g_w2bth; Tl = g_w2btl; K = DN_; N = DH_; }
    else return;
    int k = i / N, n = i % N;
    split_store(&Th[(size_t)n * K + k], &Tl[(size_t)n * K + k], W[i]);
}

// ---------------- aggregation (writes bf16 split directly) ----------------
__global__ void aggregate_kernel(const float* __restrict__ nf,
                                 const float* __restrict__ rel,
                                 const int* __restrict__ nb1, const int* __restrict__ rl1, const void* __restrict__ m1,
                                 const int* __restrict__ nb2, const int* __restrict__ rl2, const void* __restrict__ m2,
                                 const int* __restrict__ selfids) {
    int b = blockIdx.x;
    const int* nb; const int* rl; const void* m; bf16* oh; bf16* ol;
    if (b < BN_) { nb = nb1; rl = rl1; m = m1; oh = g_v1h; ol = g_v1l; }
    else         { b -= BN_; nb = nb2; rl = rl2; m = m2; oh = g_v2h; ol = g_v2l; }

    __shared__ int s_nb[KN_], s_rl[KN_], s_m[KN_];
    __shared__ int s_cnt;
    int t = threadIdx.x;
    if (t < KN_) {
        int mk;
        if (g_mask_u8) mk = ((const unsigned char*)m)[b * KN_ + t];
        else           mk = ((const int*)m)[b * KN_ + t];
        mk = (mk != 0);
        s_m[t]  = mk;
        s_nb[t] = nb[b * KN_ + t];
        s_rl[t] = rl[b * KN_ + t];
        unsigned bal = __ballot_sync(0xFFFFFFFFu, mk);
        if (t == 0) s_cnt = __popc(bal);
    }
    __syncthreads();
    int cnt = s_cnt;
    int d = t;
    float acc = 0.f;
#pragma unroll 4
    for (int k = 0; k < KN_; k++) {
        if (s_m[k])
            acc += nf[(size_t)s_nb[k] * DN_ + d] + rel[s_rl[k] * DN_ + d];
    }
    float res;
    if (cnt > 0) res = acc / (float)cnt;
    else         res = nf[(size_t)selfids[b] * DN_ + d];
    split_store(&oh[(size_t)b * DN_ + d], &ol[(size_t)b * DN_ + d], res);
}

// ---------------- mma helpers ----------------
__device__ __forceinline__ void mma16816(float c[4], unsigned a0, unsigned a1, unsigned a2, unsigned a3,
                                         unsigned b0, unsigned b1) {
    asm volatile("mma.sync.aligned.m16n8k16.row.col.f32.bf16.bf16.f32 "
                 "{%0,%1,%2,%3}, {%4,%5,%6,%7}, {%8,%9}, {%0,%1,%2,%3};\n"
                 : "+f"(c[0]), "+f"(c[1]), "+f"(c[2]), "+f"(c[3])
                 : "r"(a0), "r"(a1), "r"(a2), "r"(a3), "r"(b0), "r"(b1));
}

#define TS 40   // smem tile stride (32 + 8 pad)

__device__ __forceinline__ void load_tile(bf16* S, const bf16* G, int row0, int ld, int k0, int tid) {
#pragma unroll
    for (int i = 0; i < 2; i++) {
        int e = tid + i * 256;
        int row = e >> 2, seg = e & 3;
        *(uint4*)(S + row * TS + seg * 8) =
            *(const uint4*)(G + (size_t)(row0 + row) * ld + k0 + seg * 8);
    }
}

__device__ __forceinline__ void ldfragA(unsigned a[4], const bf16* S, int rb, int kk, int grp, int qp) {
    a[0] = *(const unsigned*)(S + (rb + grp) * TS + kk + qp);
    a[1] = *(const unsigned*)(S + (rb + grp + 8) * TS + kk + qp);
    a[2] = *(const unsigned*)(S + (rb + grp) * TS + kk + 8 + qp);
    a[3] = *(const unsigned*)(S + (rb + grp + 8) * TS + kk + 8 + qp);
}
__device__ __forceinline__ void ldfragB(unsigned b[2], const bf16* S, int nb, int kk, int grp, int qp) {
    b[0] = *(const unsigned*)(S + (nb + grp) * TS + kk + qp);
    b[1] = *(const unsigned*)(S + (nb + grp) * TS + kk + 8 + qp);
}

// split-bf16 mainloop: 3 passes (Ah*Bh + Ah*Bl + Al*Bh) over one 128x128xK tile
__device__ __forceinline__ void mma_mainloop(
        float c[4][4][4],
        const bf16* Ah, const bf16* Al, const bf16* Bh, const bf16* Bl,
        bf16* sAh, bf16* sAl, bf16* sBh, bf16* sBl,
        int bm, int bn, int K, int tid, int wr, int wc, int grp, int qp) {
    for (int k0 = 0; k0 < K; k0 += 32) {
        load_tile(sAh, Ah, bm, K, k0, tid);
        load_tile(sAl, Al, bm, K, k0, tid);
        load_tile(sBh, Bh, bn, K, k0, tid);
        load_tile(sBl, Bl, bn, K, k0, tid);
        __syncthreads();
#pragma unroll
        for (int kk = 0; kk < 32; kk += 16) {
            unsigned ah[4][4], bh[4][2];
#pragma unroll
            for (int ms = 0; ms < 4; ms++) ldfragA(ah[ms], sAh, wr * 64 + ms * 16, kk, grp, qp);
#pragma unroll
            for (int ns = 0; ns < 4; ns++) ldfragB(bh[ns], sBh, wc * 32 + ns * 8, kk, grp, qp);
#pragma unroll
            for (int ms = 0; ms < 4; ms++)
#pragma unroll
                for (int ns = 0; ns < 4; ns++)
                    mma16816(c[ms][ns], ah[ms][0], ah[ms][1], ah[ms][2], ah[ms][3], bh[ns][0], bh[ns][1]);
            {
                unsigned bl[4][2];
#pragma unroll
                for (int ns = 0; ns < 4; ns++) ldfragB(bl[ns], sBl, wc * 32 + ns * 8, kk, grp, qp);
#pragma unroll
                for (int ms = 0; ms < 4; ms++)
#pragma unroll
                    for (int ns = 0; ns < 4; ns++)
                        mma16816(c[ms][ns], ah[ms][0], ah[ms][1], ah[ms][2], ah[ms][3], bl[ns][0], bl[ns][1]);
            }
            {
                unsigned al[4][4];
#pragma unroll
                for (int ms = 0; ms < 4; ms++) ldfragA(al[ms], sAl, wr * 64 + ms * 16, kk, grp, qp);
#pragma unroll
                for (int ms = 0; ms < 4; ms++)
#pragma unroll
                    for (int ns = 0; ns < 4; ns++)
                        mma16816(c[ms][ns], al[ms][0], al[ms][1], al[ms][2], al[ms][3], bh[ns][0], bh[ns][1]);
            }
        }
        __syncthreads();
    }
}

// ---------------- proj-a (both views): h = relu(v @ Wa^T + ba), split output ----------------
__global__ void __launch_bounds__(256) mma_projA_kernel(
        const float* __restrict__ b1a, const float* __restrict__ b2a) {
    __shared__ __align__(16) bf16 sAh[128 * TS], sAl[128 * TS], sBh[128 * TS], sBl[128 * TS];
    int tid = threadIdx.x;
    int lane = tid & 31, w = tid >> 5;
    int wr = w >> 2, wc = w & 3;
    int grp = lane >> 2, qp = (lane & 3) * 2;
    int bm = blockIdx.x * 128, bn = blockIdx.y * 128;
    int view = blockIdx.z;
    const bf16* Ah = view ? g_v2h : g_v1h;
    const bf16* Al = view ? g_v2l : g_v1l;
    const bf16* Bh = view ? g_w2ath : g_w1ath;
    const bf16* Bl = view ? g_w2atl : g_w1atl;
    const float* bias = view ? b2a : b1a;
    bf16* Ch = view ? g_h2h : g_h1h;
    bf16* Cl = view ? g_h2l : g_h1l;

    float c[4][4][4] = {};
    mma_mainloop(c, Ah, Al, Bh, Bl, sAh, sAl, sBh, sBl, bm, bn, DN_, tid, wr, wc, grp, qp);

#pragma unroll
    for (int ms = 0; ms < 4; ms++) {
#pragma unroll
        for (int ns = 0; ns < 4; ns++) {
            int col = bn + wc * 32 + ns * 8 + qp;
            float b0 = bias[col], b1 = bias[col + 1];
#pragma unroll
            for (int h = 0; h < 2; h++) {
                int row = bm + wr * 64 + ms * 16 + grp + 8 * h;
                float v0 = fmaxf(c[ms][ns][2 * h + 0] + b0, 0.f);
                float v1 = fmaxf(c[ms][ns][2 * h + 1] + b1, 0.f);
                bf16 h0 = __float2bfloat16(v0), h1 = __float2bfloat16(v1);
                bf16 l0 = __float2bfloat16(v0 - __bfloat162float(h0));
                bf16 l1 = __float2bfloat16(v1 - __bfloat162float(h1));
                __nv_bfloat162 hp; hp.x = h0; hp.y = h1;
                __nv_bfloat162 lp; lp.x = l0; lp.y = l1;
                *(__nv_bfloat162*)(Ch + (size_t)row * DN_ + col) = hp;
                *(__nv_bfloat162*)(Cl + (size_t)row * DN_ + col) = lp;
            }
        }
    }
}

// ---------------- proj-b (both views) + fused L2-normalize + split ----------------
// N = DH_ = 128 = one block tile covers the full output row -> normalize in-block.
__global__ void __launch_bounds__(256) mma_projB_kernel(
        const float* __restrict__ b1b, const float* __restrict__ b2b) {
    __shared__ __align__(16) bf16 sAh[128 * TS], sAl[128 * TS], sBh[128 * TS], sBl[128 * TS];
    __shared__ float s_ss[128];
    int tid = threadIdx.x;
    int lane = tid & 31, w = tid >> 5;
    int wr = w >> 2, wc = w & 3;
    int grp = lane >> 2, qp = (lane & 3) * 2;
    int bm = blockIdx.x * 128;
    int view = blockIdx.z;
    const bf16* Ah = view ? g_h2h : g_h1h;
    const bf16* Al = view ? g_h2l : g_h1l;
    const bf16* Bh = view ? g_w2bth : g_w1bth;
    const bf16* Bl = view ? g_w2btl : g_w1btl;
    const float* bias = view ? b2b : b1b;
    bf16* Zh = view ? g_z2h : g_z1h;
    bf16* Zl = view ? g_z2l : g_z1l;

    if (tid < 128) s_ss[tid] = 0.f;

    float c[4][4][4] = {};
    mma_mainloop(c, Ah, Al, Bh, Bl, sAh, sAl, sBh, sBl, bm, 0, DN_, tid, wr, wc, grp, qp);

    // bias add + per-row sum of squares
    float vv[4][4][4];
#pragma unroll
    for (int ms = 0; ms < 4; ms++) {
#pragma unroll
        for (int ns = 0; ns < 4; ns++) {
            int col = wc * 32 + ns * 8 + qp;
            float b0 = bias[col], b1 = bias[col + 1];
#pragma unroll
            for (int h = 0; h < 2; h++) {
                vv[ms][ns][2 * h + 0] = c[ms][ns][2 * h + 0] + b0;
                vv[ms][ns][2 * h + 1] = c[ms][ns][2 * h + 1] + b1;
            }
        }
    }
#pragma unroll
    for (int ms = 0; ms < 4; ms++)
#pragma unroll
        for (int h = 0; h < 2; h++) {
            float ss = 0.f;
#pragma unroll
            for (int ns = 0; ns < 4; ns++) {
                float a = vv[ms][ns][2 * h + 0], b = vv[ms][ns][2 * h + 1];
                ss = fmaf(a, a, ss); ss = fmaf(b, b, ss);
            }
            ss += __shfl_xor_sync(0xFFFFFFFFu, ss, 1);
            ss += __shfl_xor_sync(0xFFFFFFFFu, ss, 2);
            if ((lane & 3) == 0)
                atomicAdd(&s_ss[wr * 64 + ms * 16 + grp + 8 * h], ss);
        }
    __syncthreads();

#pragma unroll
    for (int ms = 0; ms < 4; ms++) {
#pragma unroll
        for (int h = 0; h < 2; h++) {
            int rloc = wr * 64 + ms * 16 + grp + 8 * h;
            float rinv = rsqrtf(s_ss[rloc]);
            int row = bm + rloc;
#pragma unroll
            for (int ns = 0; ns < 4; ns++) {
                int col = wc * 32 + ns * 8 + qp;
                float v0 = vv[ms][ns][2 * h + 0] * rinv;
                float v1 = vv[ms][ns][2 * h + 1] * rinv;
                bf16 h0 = __float2bfloat16(v0), h1 = __float2bfloat16(v1);
                bf16 l0 = __float2bfloat16(v0 - __bfloat162float(h0));
                bf16 l1 = __float2bfloat16(v1 - __bfloat162float(h1));
                __nv_bfloat162 hp; hp.x = h0; hp.y = h1;
                __nv_bfloat162 lp; lp.x = l0; lp.y = l1;
                *(__nv_bfloat162*)(Zh + (size_t)row * DH_ + col) = hp;
                *(__nv_bfloat162*)(Zl + (size_t)row * DH_ + col) = lp;
            }
        }
    }
}

// ---------------- fused split-bf16 sim GEMM + shifted-exp LSE ----------------
__global__ void __launch_bounds__(256) sim_lse_kernel() {
    __shared__ __align__(16) bf16 sAh[128 * TS], sAl[128 * TS], sBh[128 * TS], sBl[128 * TS];
    __shared__ float s_rs[128], s_cs[128];
    int tid = threadIdx.x;
    int lane = tid & 31, w = tid >> 5;
    int wr = w >> 2, wc = w & 3;
    int grp = lane >> 2, qp = (lane & 3) * 2;
    int bm = blockIdx.x * 128, bn = blockIdx.y * 128;
    if (tid < 128) { s_rs[tid] = 0.f; s_cs[tid] = 0.f; }

    float c[4][4][4] = {};
    mma_mainloop(c, g_z1h, g_z1l, g_z2h, g_z2l, sAh, sAl, sBh, sBl, bm, bn, DH_, tid, wr, wc, grp, qp);

    float rs[4][2] = {}, cs[4][2] = {};
#pragma unroll
    for (int ms = 0; ms < 4; ms++) {
#pragma unroll
        for (int ns = 0; ns < 4; ns++) {
#pragma unroll
            for (int r = 0; r < 4; r++) {
                int h = r >> 1, p = r & 1;
                int row = bm + wr * 64 + ms * 16 + grp + 8 * h;
                int col = bn + wc * 32 + ns * 8 + qp + p;
                float s = c[ms][ns][r] * INV_T;
                if (row == col) g_diag[row] = s;
                float ev = __expf(s - INV_T);
                rs[ms][h] += ev;
                cs[ns][p] += ev;
            }
        }
    }
#pragma unroll
    for (int ms = 0; ms < 4; ms++)
#pragma unroll
        for (int h = 0; h < 2; h++) {
            float v = rs[ms][h];
            v += __shfl_xor_sync(0xFFFFFFFFu, v, 1);
            v += __shfl_xor_sync(0xFFFFFFFFu, v, 2);
            if ((lane & 3) == 0)
                atomicAdd(&s_rs[wr * 64 + ms * 16 + grp + 8 * h], v);
        }
#pragma unroll
    for (int ns = 0; ns < 4; ns++)
#pragma unroll
        for (int p = 0; p < 2; p++) {
            float v = cs[ns][p];
            v += __shfl_xor_sync(0xFFFFFFFFu, v, 4);
            v += __shfl_xor_sync(0xFFFFFFFFu, v, 8);
            v += __shfl_xor_sync(0xFFFFFFFFu, v, 16);
            if (grp == 0)
                atomicAdd(&s_cs[wc * 32 + ns * 8 + qp + p], v);
        }
    __syncthreads();
    if (tid < 128) {
        atomicAdd(&g_rowsum[bm + tid], s_rs[tid]);
        atomicAdd(&g_colsum[bn + tid], s_cs[tid]);
    }
}

// ---------------- final loss reduce ----------------
__global__ void loss_kernel(float* __restrict__ out) {
    float acc = 0.f;
    for (int i = threadIdx.x; i < BN_; i += 256) {
        acc += 0.5f * (logf(g_rowsum[i]) + logf(g_colsum[i])) + INV_T - g_diag[i];
    }
#pragma unroll
    for (int off = 16; off; off >>= 1) acc += __shfl_xor_sync(0xFFFFFFFFu, acc, off);
    __shared__ float wsum[8];
    if ((threadIdx.x & 31) == 0) wsum[threadIdx.x >> 5] = acc;
    __syncthreads();
    if (threadIdx.x == 0) {
        float tot = 0.f;
        for (int k = 0; k < 8; k++) tot += wsum[k];
        out[0] = tot / (float)BN_;
    }
}

// ---------------- launch ----------------
extern "C" void kernel_launch(void* const* d_in, const int* in_sizes, int n_in,
                              void* d_out, int out_size) {
    const float* nf   = (const float*)d_in[0];
    const float* rel  = (const float*)d_in[1];
    const int*   nb1  = (const int*)d_in[2];
    const int*   rl1  = (const int*)d_in[3];
    const void*  m1   = d_in[4];
    const int*   nb2  = (const int*)d_in[5];
    const int*   rl2  = (const int*)d_in[6];
    const void*  m2   = d_in[7];
    const int*   self_ = (const int*)d_in[8];
    const float* W1a  = (const float*)d_in[9];
    const float* b1a  = (const float*)d_in[10];
    const float* W1b  = (const float*)d_in[11];
    const float* b1b  = (const float*)d_in[12];
    const float* W2a  = (const float*)d_in[13];
    const float* b2a  = (const float*)d_in[14];
    const float* W2b  = (const float*)d_in[15];
    const float* b2b  = (const float*)d_in[16];

    detect_mask_kernel<<<1, 256>>>((const unsigned int*)m1);                       // 0
    prep_kernel<<<768, 256>>>(W1a, W1b, W2a, W2b);                                 // 1
    aggregate_kernel<<<2 * BN_, 256>>>(nf, rel, nb1, rl1, m1, nb2, rl2, m2, self_);// 2
    mma_projA_kernel<<<dim3(BN_ / 128, DN_ / 128, 2), 256>>>(b1a, b2a);            // 3
    mma_projB_kernel<<<dim3(BN_ / 128, 1, 2), 256>>>(b1b, b2b);                    // 4
    sim_lse_kernel<<<dim3(BN_ / 128, BN_ / 128), 256>>>();                         // 5 (profiled)
    loss_kernel<<<1, 256>>>((float*)d_out);                                        // 6
}

// round 8
// speedup vs baseline: 2.0983x; 1.2710x over previous
#include <cuda_runtime.h>
#include <cuda_bf16.h>
#include <math.h>
#include <stdint.h>

#define BN_ 4096
#define KN_ 32
#define DN_ 256
#define DH_ 128
#define INV_T 14.285714285714286f
#define TS 40   // smem tile stride in bf16 (32 + 8 pad; 80B rows -> LDSM conflict-free)

typedef __nv_bfloat16 bf16;

// ---------------- scratch ----------------
__device__ __align__(16) bf16 g_v1h[BN_ * DN_];
__device__ __align__(16) bf16 g_v1l[BN_ * DN_];
__device__ __align__(16) bf16 g_v2h[BN_ * DN_];
__device__ __align__(16) bf16 g_v2l[BN_ * DN_];
__device__ __align__(16) bf16 g_h1h[BN_ * DN_];
__device__ __align__(16) bf16 g_h1l[BN_ * DN_];
__device__ __align__(16) bf16 g_h2h[BN_ * DN_];
__device__ __align__(16) bf16 g_h2l[BN_ * DN_];
__device__ __align__(16) bf16 g_z1h[BN_ * DH_];
__device__ __align__(16) bf16 g_z1l[BN_ * DH_];
__device__ __align__(16) bf16 g_z2h[BN_ * DH_];
__device__ __align__(16) bf16 g_z2l[BN_ * DH_];
__device__ __align__(16) bf16 g_w1ath[DN_ * DN_];
__device__ __align__(16) bf16 g_w1atl[DN_ * DN_];
__device__ __align__(16) bf16 g_w1bth[DH_ * DN_];
__device__ __align__(16) bf16 g_w1btl[DH_ * DN_];
__device__ __align__(16) bf16 g_w2ath[DN_ * DN_];
__device__ __align__(16) bf16 g_w2atl[DN_ * DN_];
__device__ __align__(16) bf16 g_w2bth[DH_ * DN_];
__device__ __align__(16) bf16 g_w2btl[DH_ * DN_];
__device__ float g_rowsum[BN_];
__device__ float g_colsum[BN_];
__device__ float g_diag[BN_];
__device__ int   g_mask_u8;

__device__ __forceinline__ void split_store(bf16* ph, bf16* pl, float v) {
    bf16 h = __float2bfloat16(v);
    *ph = h;
    *pl = __float2bfloat16(v - __bfloat162float(h));
}

// ---------------- prep: mask detect + zero accumulators + weight split/transpose ----------------
__global__ void prep_kernel(const float* __restrict__ W1a, const float* __restrict__ W1b,
                            const float* __restrict__ W2a, const float* __restrict__ W2b,
                            const unsigned int* __restrict__ m1) {
    if (blockIdx.x == 0) {
        __shared__ int sf;
        if (threadIdx.x == 0) sf = 0;
        __syncthreads();
        int f = 0;
        for (int i = threadIdx.x; i < 4096; i += 256)
            if (m1[i] > 1u) f = 1;
        if (f) sf = 1;
        __syncthreads();
        if (threadIdx.x == 0) g_mask_u8 = sf;
    }
    int idx = blockIdx.x * 256 + threadIdx.x;
    if (idx < BN_) { g_rowsum[idx] = 0.f; g_colsum[idx] = 0.f; }
    int i = idx;
    const float* W; bf16* Th; bf16* Tl; int K, N;
    if (i < DN_ * DN_)                     { W = W1a; Th = g_w1ath; Tl = g_w1atl; K = DN_; N = DN_; }
    else if ((i -= DN_ * DN_) < DN_ * DH_) { W = W1b; Th = g_w1bth; Tl = g_w1btl; K = DN_; N = DH_; }
    else if ((i -= DN_ * DH_) < DN_ * DN_) { W = W2a; Th = g_w2ath; Tl = g_w2atl; K = DN_; N = DN_; }
    else if ((i -= DN_ * DN_) < DN_ * DH_) { W = W2b; Th = g_w2bth; Tl = g_w2btl; K = DN_; N = DH_; }
    else return;
    int k = i / N, n = i % N;
    split_store(&Th[(size_t)n * K + k], &Tl[(size_t)n * K + k], W[i]);
}

// ---------------- aggregation ----------------
__global__ void aggregate_kernel(const float* __restrict__ nf,
                                 const float* __restrict__ rel,
                                 const int* __restrict__ nb1, const int* __restrict__ rl1, const void* __restrict__ m1,
                                 const int* __restrict__ nb2, const int* __restrict__ rl2, const void* __restrict__ m2,
                                 const int* __restrict__ selfids) {
    int b = blockIdx.x;
    const int* nb; const int* rl; const void* m; bf16* oh; bf16* ol;
    if (b < BN_) { nb = nb1; rl = rl1; m = m1; oh = g_v1h; ol = g_v1l; }
    else         { b -= BN_; nb = nb2; rl = rl2; m = m2; oh = g_v2h; ol = g_v2l; }

    __shared__ int s_nb[KN_], s_rl[KN_], s_m[KN_];
    __shared__ int s_cnt;
    int t = threadIdx.x;
    if (t < KN_) {
        int mk;
        if (g_mask_u8) mk = ((const unsigned char*)m)[b * KN_ + t];
        else           mk = ((const int*)m)[b * KN_ + t];
        mk = (mk != 0);
        s_m[t]  = mk;
        s_nb[t] = nb[b * KN_ + t];
        s_rl[t] = rl[b * KN_ + t];
        unsigned bal = __ballot_sync(0xFFFFFFFFu, mk);
        if (t == 0) s_cnt = __popc(bal);
    }
    __syncthreads();
    int cnt = s_cnt;
    int d = t;
    float acc = 0.f;
#pragma unroll 4
    for (int k = 0; k < KN_; k++) {
        if (s_m[k])
            acc += nf[(size_t)s_nb[k] * DN_ + d] + rel[s_rl[k] * DN_ + d];
    }
    float res;
    if (cnt > 0) res = acc / (float)cnt;
    else         res = nf[(size_t)selfids[b] * DN_ + d];
    split_store(&oh[(size_t)b * DN_ + d], &ol[(size_t)b * DN_ + d], res);
}

// ---------------- async-copy / ldmatrix / mma primitives ----------------
__device__ __forceinline__ void cp16(uint32_t s, const void* g) {
    asm volatile("cp.async.cg.shared.global [%0], [%1], 16;\n" :: "r"(s), "l"(g));
}
__device__ __forceinline__ void cpcommit() {
    asm volatile("cp.async.commit_group;\n" ::: "memory");
}
template <int N>
__device__ __forceinline__ void cpwait() {
    asm volatile("cp.async.wait_group %0;\n" :: "n"(N) : "memory");
}
__device__ __forceinline__ void ldsm4(unsigned r[4], uint32_t a) {
    asm volatile("ldmatrix.sync.aligned.m8n8.x4.shared.b16 {%0,%1,%2,%3}, [%4];\n"
                 : "=r"(r[0]), "=r"(r[1]), "=r"(r[2]), "=r"(r[3]) : "r"(a));
}
__device__ __forceinline__ void mma16816(float c[4], unsigned a0, unsigned a1, unsigned a2, unsigned a3,
                                         unsigned b0, unsigned b1) {
    asm volatile("mma.sync.aligned.m16n8k16.row.col.f32.bf16.bf16.f32 "
                 "{%0,%1,%2,%3}, {%4,%5,%6,%7}, {%8,%9}, {%0,%1,%2,%3};\n"
                 : "+f"(c[0]), "+f"(c[1]), "+f"(c[2]), "+f"(c[3])
                 : "r"(a0), "r"(a1), "r"(a2), "r"(a3), "r"(b0), "r"(b1));
}

// issue one stage of cp.async loads: A(h,l) BM rows, B(h,l) BN rows, 32 k-cols each
template <int BM, int BN>
__device__ __forceinline__ void issue_stage(uint32_t sb,
        const bf16* Ah, const bf16* Al, const bf16* Bh, const bf16* Bl,
        int bm, int bn, int ld, int k0, int tid) {
#pragma unroll
    for (int idx = tid; idx < BM * 4; idx += 256) {
        int row = idx >> 2, seg = idx & 3;
        size_t go = (size_t)(bm + row) * ld + k0 + seg * 8;
        uint32_t so = (uint32_t)(row * TS + seg * 8) * 2;
        cp16(sb + so, Ah + go);
        cp16(sb + BM * TS * 2 + so, Al + go);
    }
#pragma unroll
    for (int idx = tid; idx < BN * 4; idx += 256) {
        int row = idx >> 2, seg = idx & 3;
        size_t go = (size_t)(bn + row) * ld + k0 + seg * 8;
        uint32_t so = (uint32_t)(row * TS + seg * 8) * 2;
        cp16(sb + BM * TS * 4 + so, Bh + go);
        cp16(sb + BM * TS * 4 + BN * TS * 2 + so, Bl + go);
    }
}

// 2-stage pipelined split-bf16 MMA mainloop (Ah*Bh + Ah*Bl + Al*Bh)
template <int BM, int BN, int MS, int NS, int WCOLS, int NIT>
__device__ __forceinline__ void mma_pipe(float (&c)[MS][NS][4],
        const bf16* Ah, const bf16* Al, const bf16* Bh, const bf16* Bl,
        int bm, int bn, int ld, char* smem_dyn, int tid) {
    constexpr int SSB = (BM + BN) * TS * 4;   // bytes per stage
    uint32_t sb0 = (uint32_t)__cvta_generic_to_shared(smem_dyn);
    int lane = tid & 31, w = tid >> 5;
    int wr = w / WCOLS, wc = w % WCOLS;
    int rowA = (lane & 7) + ((lane >> 3) & 1) * 8;
    int kA   = (lane >> 4) * 8;
    int rowB = (lane & 7) + (lane >> 4) * 8;
    int kB   = ((lane >> 3) & 1) * 8;

    issue_stage<BM, BN>(sb0, Ah, Al, Bh, Bl, bm, bn, ld, 0, tid);
    cpcommit();

#pragma unroll 1
    for (int it = 0; it < NIT; ++it) {
        uint32_t scur = sb0 + (it & 1) * SSB;
        if (it + 1 < NIT) {
            issue_stage<BM, BN>(sb0 + ((it + 1) & 1) * SSB, Ah, Al, Bh, Bl, bm, bn, ld, (it + 1) * 32, tid);
            cpcommit();
            cpwait<1>();
        } else {
            cpwait<0>();
        }
        __syncthreads();
        uint32_t sAh_ = scur;
        uint32_t sAl_ = scur + BM * TS * 2;
        uint32_t sBh_ = scur + BM * TS * 4;
        uint32_t sBl_ = sBh_ + BN * TS * 2;
#pragma unroll
        for (int kk = 0; kk < 32; kk += 16) {
            unsigned ah[MS][4];
#pragma unroll
            for (int ms = 0; ms < MS; ms++)
                ldsm4(ah[ms], sAh_ + (uint32_t)(((wr * MS + ms) * 16 + rowA) * TS + kk + kA) * 2);
            unsigned bh[NS][2];
#pragma unroll
            for (int np = 0; np < NS / 2; np++) {
                unsigned r[4];
                ldsm4(r, sBh_ + (uint32_t)((wc * NS * 8 + np * 16 + rowB) * TS + kk + kB) * 2);
                bh[2 * np][0] = r[0]; bh[2 * np][1] = r[1];
                bh[2 * np + 1][0] = r[2]; bh[2 * np + 1][1] = r[3];
            }
#pragma unroll
            for (int ms = 0; ms < MS; ms++)
#pragma unroll
                for (int ns = 0; ns < NS; ns++)
                    mma16816(c[ms][ns], ah[ms][0], ah[ms][1], ah[ms][2], ah[ms][3], bh[ns][0], bh[ns][1]);
            {
                unsigned bl[NS][2];
#pragma unroll
                for (int np = 0; np < NS / 2; np++) {
                    unsigned r[4];
                    ldsm4(r, sBl_ + (uint32_t)((wc * NS * 8 + np * 16 + rowB) * TS + kk + kB) * 2);
                    bl[2 * np][0] = r[0]; bl[2 * np][1] = r[1];
                    bl[2 * np + 1][0] = r[2]; bl[2 * np + 1][1] = r[3];
                }
#pragma unroll
                for (int ms = 0; ms < MS; ms++)
#pragma unroll
                    for (int ns = 0; ns < NS; ns++)
                        mma16816(c[ms][ns], ah[ms][0], ah[ms][1], ah[ms][2], ah[ms][3], bl[ns][0], bl[ns][1]);
            }
            {
                unsigned al[MS][4];
#pragma unroll
                for (int ms = 0; ms < MS; ms++)
                    ldsm4(al[ms], sAl_ + (uint32_t)(((wr * MS + ms) * 16 + rowA) * TS + kk + kA) * 2);
#pragma unroll
                for (int ms = 0; ms < MS; ms++)
#pragma unroll
                    for (int ns = 0; ns < NS; ns++)
                        mma16816(c[ms][ns], al[ms][0], al[ms][1], al[ms][2], al[ms][3], bh[ns][0], bh[ns][1]);
            }
        }
        __syncthreads();
    }
}

// ---------------- proj-a: 128x64 tiles, grid (32,4,2) ----------------
__global__ void __launch_bounds__(256, 2) mma_projA_kernel(
        const float* __restrict__ b1a, const float* __restrict__ b2a) {
    extern __shared__ char smem_dyn[];
    int tid = threadIdx.x;
    int lane = tid & 31, w = tid >> 5;
    int wr = w >> 1, wc = w & 1;
    int grp = lane >> 2, qp = (lane & 3) * 2;
    int bm = blockIdx.x * 128, bn = blockIdx.y * 64;
    int view = blockIdx.z;
    const bf16* Ah = view ? g_v2h : g_v1h;
    const bf16* Al = view ? g_v2l : g_v1l;
    const bf16* Bh = view ? g_w2ath : g_w1ath;
    const bf16* Bl = view ? g_w2atl : g_w1atl;
    const float* bias = view ? b2a : b1a;
    bf16* Ch = view ? g_h2h : g_h1h;
    bf16* Cl = view ? g_h2l : g_h1l;

    float c[2][4][4] = {};
    mma_pipe<128, 64, 2, 4, 2, 8>(c, Ah, Al, Bh, Bl, bm, bn, DN_, smem_dyn, tid);

#pragma unroll
    for (int ms = 0; ms < 2; ms++) {
#pragma unroll
        for (int ns = 0; ns < 4; ns++) {
            int col = bn + wc * 32 + ns * 8 + qp;
            float b0 = bias[col], b1 = bias[col + 1];
#pragma unroll
            for (int h = 0; h < 2; h++) {
                int row = bm + (wr * 2 + ms) * 16 + grp + 8 * h;
                float v0 = fmaxf(c[ms][ns][2 * h + 0] + b0, 0.f);
                float v1 = fmaxf(c[ms][ns][2 * h + 1] + b1, 0.f);
                bf16 h0 = __float2bfloat16(v0), h1 = __float2bfloat16(v1);
                bf16 l0 = __float2bfloat16(v0 - __bfloat162float(h0));
                bf16 l1 = __float2bfloat16(v1 - __bfloat162float(h1));
                __nv_bfloat162 hp; hp.x = h0; hp.y = h1;
                __nv_bfloat162 lp; lp.x = l0; lp.y = l1;
                *(__nv_bfloat162*)(Ch + (size_t)row * DN_ + col) = hp;
                *(__nv_bfloat162*)(Cl + (size_t)row * DN_ + col) = lp;
            }
        }
    }
}

// ---------------- proj-b: 64x128 tiles + fused L2-normalize + split, grid (64,1,2) ----------------
__global__ void __launch_bounds__(256, 2) mma_projB_kernel(
        const float* __restrict__ b1b, const float* __restrict__ b2b) {
    extern __shared__ char smem_dyn[];
    __shared__ float s_ss[64];
    int tid = threadIdx.x;
    int lane = tid & 31, w = tid >> 5;
    int wr = w >> 2, wc = w & 3;
    int grp = lane >> 2, qp = (lane & 3) * 2;
    int bm = blockIdx.x * 64;
    int view = blockIdx.z;
    const bf16* Ah = view ? g_h2h : g_h1h;
    const bf16* Al = view ? g_h2l : g_h1l;
    const bf16* Bh = view ? g_w2bth : g_w1bth;
    const bf16* Bl = view ? g_w2btl : g_w1btl;
    const float* bias = view ? b2b : b1b;
    bf16* Zh = view ? g_z2h : g_z1h;
    bf16* Zl = view ? g_z2l : g_z1l;

    if (tid < 64) s_ss[tid] = 0.f;

    float c[2][4][4] = {};
    mma_pipe<64, 128, 2, 4, 4, 8>(c, Ah, Al, Bh, Bl, bm, 0, DN_, smem_dyn, tid);

    float vv[2][4][4];
#pragma unroll
    for (int ms = 0; ms < 2; ms++) {
#pragma unroll
        for (int ns = 0; ns < 4; ns++) {
            int col = wc * 32 + ns * 8 + qp;
            float b0 = bias[col], b1 = bias[col + 1];
#pragma unroll
            for (int h = 0; h < 2; h++) {
                vv[ms][ns][2 * h + 0] = c[ms][ns][2 * h + 0] + b0;
                vv[ms][ns][2 * h + 1] = c[ms][ns][2 * h + 1] + b1;
            }
        }
    }
#pragma unroll
    for (int ms = 0; ms < 2; ms++)
#pragma unroll
        for (int h = 0; h < 2; h++) {
            float ss = 0.f;
#pragma unroll
            for (int ns = 0; ns < 4; ns++) {
                float a = vv[ms][ns][2 * h + 0], b = vv[ms][ns][2 * h + 1];
                ss = fmaf(a, a, ss); ss = fmaf(b, b, ss);
            }
            ss += __shfl_xor_sync(0xFFFFFFFFu, ss, 1);
            ss += __shfl_xor_sync(0xFFFFFFFFu, ss, 2);
            if ((lane & 3) == 0)
                atomicAdd(&s_ss[(wr * 2 + ms) * 16 + grp + 8 * h], ss);
        }
    __syncthreads();

#pragma unroll
    for (int ms = 0; ms < 2; ms++) {
#pragma unroll
        for (int h = 0; h < 2; h++) {
            int rloc = (wr * 2 + ms) * 16 + grp + 8 * h;
            float rinv = rsqrtf(s_ss[rloc]);
            int row = bm + rloc;
#pragma unroll
            for (int ns = 0; ns < 4; ns++) {
                int col = wc * 32 + ns * 8 + qp;
                float v0 = vv[ms][ns][2 * h + 0] * rinv;
                float v1 = vv[ms][ns][2 * h + 1] * rinv;
                bf16 h0 = __float2bfloat16(v0), h1 = __float2bfloat16(v1);
                bf16 l0 = __float2bfloat16(v0 - __bfloat162float(h0));
                bf16 l1 = __float2bfloat16(v1 - __bfloat162float(h1));
                __nv_bfloat162 hp; hp.x = h0; hp.y = h1;
                __nv_bfloat162 lp; lp.x = l0; lp.y = l1;
                *(__nv_bfloat162*)(Zh + (size_t)row * DH_ + col) = hp;
                *(__nv_bfloat162*)(Zl + (size_t)row * DH_ + col) = lp;
            }
        }
    }
}

// ---------------- sim GEMM + shifted-exp LSE: 128x128 tiles, grid (32,32) ----------------
__global__ void __launch_bounds__(256, 2) sim_lse_kernel() {
    extern __shared__ char smem_dyn[];
    __shared__ float s_rs[128], s_cs[128];
    int tid = threadIdx.x;
    int lane = tid & 31, w = tid >> 5;
    int wr = w >> 2, wc = w & 3;
    int grp = lane >> 2, qp = (lane & 3) * 2;
    int bm = blockIdx.x * 128, bn = blockIdx.y * 128;
    if (tid < 128) { s_rs[tid] = 0.f; s_cs[tid] = 0.f; }

    float c[4][4][4] = {};
    mma_pipe<128, 128, 4, 4, 4, 4>(c, g_z1h, g_z1l, g_z2h, g_z2l, bm, bn, DH_, smem_dyn, tid);

    float rs[4][2] = {}, cs[4][2] = {};
#pragma unroll
    for (int ms = 0; ms < 4; ms++) {
#pragma unroll
        for (int ns = 0; ns < 4; ns++) {
#pragma unroll
            for (int r = 0; r < 4; r++) {
                int h = r >> 1, p = r & 1;
                int row = bm + (wr * 4 + ms) * 16 + grp + 8 * h;
                int col = bn + wc * 32 + ns * 8 + qp + p;
                float s = c[ms][ns][r] * INV_T;
                if (row == col) g_diag[row] = s;
                float ev = __expf(s - INV_T);
                rs[ms][h] += ev;
                cs[ns][p] += ev;
            }
        }
    }
#pragma unroll
    for (int ms = 0; ms < 4; ms++)
#pragma unroll
        for (int h = 0; h < 2; h++) {
            float v = rs[ms][h];
            v += __shfl_xor_sync(0xFFFFFFFFu, v, 1);
            v += __shfl_xor_sync(0xFFFFFFFFu, v, 2);
            if ((lane & 3) == 0)
                atomicAdd(&s_rs[(wr * 4 + ms) * 16 + grp + 8 * h], v);
        }
#pragma unroll
    for (int ns = 0; ns < 4; ns++)
#pragma unroll
        for (int p = 0; p < 2; p++) {
            float v = cs[ns][p];
            v += __shfl_xor_sync(0xFFFFFFFFu, v, 4);
            v += __shfl_xor_sync(0xFFFFFFFFu, v, 8);
            v += __shfl_xor_sync(0xFFFFFFFFu, v, 16);
            if (grp == 0)
                atomicAdd(&s_cs[wc * 32 + ns * 8 + qp + p], v);
        }
    __syncthreads();
    if (tid < 128) {
        atomicAdd(&g_rowsum[bm + tid], s_rs[tid]);
        atomicAdd(&g_colsum[bn + tid], s_cs[tid]);
    }
}

// ---------------- final loss reduce ----------------
__global__ void loss_kernel(float* __restrict__ out) {
    float acc = 0.f;
    for (int i = threadIdx.x; i < BN_; i += 256) {
        acc += 0.5f * (logf(g_rowsum[i]) + logf(g_colsum[i])) + INV_T - g_diag[i];
    }
#pragma unroll
    for (int off = 16; off; off >>= 1) acc += __shfl_xor_sync(0xFFFFFFFFu, acc, off);
    __shared__ float wsum[8];
    if ((threadIdx.x & 31) == 0) wsum[threadIdx.x >> 5] = acc;
    __syncthreads();
    if (threadIdx.x == 0) {
        float tot = 0.f;
        for (int k = 0; k < 8; k++) tot += wsum[k];
        out[0] = tot / (float)BN_;
    }
}

// ---------------- launch ----------------
extern "C" void kernel_launch(void* const* d_in, const int* in_sizes, int n_in,
                              void* d_out, int out_size) {
    const float* nf   = (const float*)d_in[0];
    const float* rel  = (const float*)d_in[1];
    const int*   nb1  = (const int*)d_in[2];
    const int*   rl1  = (const int*)d_in[3];
    const void*  m1   = d_in[4];
    const int*   nb2  = (const int*)d_in[5];
    const int*   rl2  = (const int*)d_in[6];
    const void*  m2   = d_in[7];
    const int*   self_ = (const int*)d_in[8];
    const float* W1a  = (const float*)d_in[9];
    const float* b1a  = (const float*)d_in[10];
    const float* W1b  = (const float*)d_in[11];
    const float* b1b  = (const float*)d_in[12];
    const float* W2a  = (const float*)d_in[13];
    const float* b2a  = (const float*)d_in[14];
    const float* W2b  = (const float*)d_in[15];
    const float* b2b  = (const float*)d_in[16];

    const int smemA  = (128 + 64) * TS * 4 * 2;   // 61440
    const int smemB  = (64 + 128) * TS * 4 * 2;   // 61440
    const int smemS  = (128 + 128) * TS * 4 * 2;  // 81920
    cudaFuncSetAttribute(mma_projA_kernel, cudaFuncAttributeMaxDynamicSharedMemorySize, smemA);
    cudaFuncSetAttribute(mma_projB_kernel, cudaFuncAttributeMaxDynamicSharedMemorySize, smemB);
    cudaFuncSetAttribute(sim_lse_kernel,   cudaFuncAttributeMaxDynamicSharedMemorySize, smemS);

    prep_kernel<<<768, 256>>>(W1a, W1b, W2a, W2b, (const unsigned int*)m1);
    aggregate_kernel<<<2 * BN_, 256>>>(nf, rel, nb1, rl1, m1, nb2, rl2, m2, self_);
    mma_projA_kernel<<<dim3(32, 4, 2), 256, smemA>>>(b1a, b2a);
    mma_projB_kernel<<<dim3(64, 1, 2), 256, smemB>>>(b1b, b2b);
    sim_lse_kernel<<<dim3(32, 32), 256, smemS>>>();
    loss_kernel<<<1, 256>>>((float*)d_out);
}

// round 10
// speedup vs baseline: 2.1595x; 1.0291x over previous
#include <cuda_runtime.h>
#include <cuda_bf16.h>
#include <math.h>
#include <stdint.h>

#define BN_ 4096
#define KN_ 32
#define DN_ 256
#define DH_ 128
#define NREL_ 9
#define INV_T 14.285714285714286f
#define TS 40   // smem tile stride in bf16 (32 + 8 pad; LDSM conflict-free)

typedef __nv_bfloat16 bf16;

// ---------------- scratch ----------------
__device__ __align__(16) bf16 g_v1h[BN_ * DN_];
__device__ __align__(16) bf16 g_v1l[BN_ * DN_];
__device__ __align__(16) bf16 g_v2h[BN_ * DN_];
__device__ __align__(16) bf16 g_v2l[BN_ * DN_];
__device__ __align__(16) bf16 g_h1h[BN_ * DN_];
__device__ __align__(16) bf16 g_h1l[BN_ * DN_];
__device__ __align__(16) bf16 g_h2h[BN_ * DN_];
__device__ __align__(16) bf16 g_h2l[BN_ * DN_];
__device__ __align__(16) bf16 g_z1h[BN_ * DH_];
__device__ __align__(16) bf16 g_z1l[BN_ * DH_];
__device__ __align__(16) bf16 g_z2h[BN_ * DH_];
__device__ __align__(16) bf16 g_z2l[BN_ * DH_];
__device__ __align__(16) bf16 g_w1ath[DN_ * DN_];
__device__ __align__(16) bf16 g_w1atl[DN_ * DN_];
__device__ __align__(16) bf16 g_w1bth[DH_ * DN_];
__device__ __align__(16) bf16 g_w1btl[DH_ * DN_];
__device__ __align__(16) bf16 g_w2ath[DN_ * DN_];
__device__ __align__(16) bf16 g_w2atl[DN_ * DN_];
__device__ __align__(16) bf16 g_w2bth[DH_ * DN_];
__device__ __align__(16) bf16 g_w2btl[DH_ * DN_];
__device__ float g_rowsum[BN_];
__device__ float g_colsum[BN_];
__device__ float g_diag[BN_];
__device__ int   g_mask_u8;

__device__ __forceinline__ void split_store(bf16* ph, bf16* pl, float v) {
    bf16 h = __float2bfloat16(v);
    *ph = h;
    *pl = __float2bfloat16(v - __bfloat162float(h));
}

// ---------------- prep: mask detect + zero + tiled weight split/transpose ----------------
// 48 blocks: W1a 16 tiles(64x64), W1b 8, W2a 16, W2b 8. Coalesced smem transpose.
__global__ void prep_kernel(const float* __restrict__ W1a, const float* __restrict__ W1b,
                            const float* __restrict__ W2a, const float* __restrict__ W2b,
                            const unsigned int* __restrict__ m1) {
    int blk = blockIdx.x;
    int t = threadIdx.x;

    // zero accumulators (48*256 = 12288 >= 4096)
    int zi = blk * 256 + t;
    if (zi < BN_) { g_rowsum[zi] = 0.f; g_colsum[zi] = 0.f; }

    // mask dtype detect (block 0)
    __shared__ int sf;
    if (t == 0) sf = 0;
    __syncthreads();
    if (blk == 0) {
        int f = 0;
        for (int i = t; i < 4096; i += 256)
            if (m1[i] > 1u) f = 1;
        if (f) sf = 1;
    }
    __syncthreads();
    if (blk == 0 && t == 0) g_mask_u8 = sf;

    // tile decode
    const float* W; bf16* Th; bf16* Tl; int N, tile;
    const int K = DN_;
    if (blk < 16)      { W = W1a; Th = g_w1ath; Tl = g_w1atl; N = 256; tile = blk; }
    else if (blk < 24) { W = W1b; Th = g_w1bth; Tl = g_w1btl; N = 128; tile = blk - 16; }
    else if (blk < 40) { W = W2a; Th = g_w2ath; Tl = g_w2atl; N = 256; tile = blk - 24; }
    else               { W = W2b; Th = g_w2bth; Tl = g_w2btl; N = 128; tile = blk - 40; }
    int tn = N / 64;
    int k0 = (tile / tn) * 64, n0 = (tile % tn) * 64;

    __shared__ float s[64][65];
#pragma unroll
    for (int i = 0; i < 16; i++) {
        int idx = t + i * 256;
        int r = idx >> 6, c = idx & 63;
        s[r][c] = W[(size_t)(k0 + r) * N + n0 + c];
    }
    __syncthreads();
#pragma unroll
    for (int i = 0; i < 16; i++) {
        int idx = t + i * 256;
        int n = idx >> 6, k = idx & 63;
        split_store(&Th[(size_t)(n0 + n) * K + k0 + k],
                    &Tl[(size_t)(n0 + n) * K + k0 + k], s[k][n]);
    }
}

// ---------------- aggregation: compacted masked gather + rel-count reconstruction ----------------
__global__ void aggregate_kernel(const float* __restrict__ nf,
                                 const float* __restrict__ rel,
                                 const int* __restrict__ nb1, const int* __restrict__ rl1, const void* __restrict__ m1,
                                 const int* __restrict__ nb2, const int* __restrict__ rl2, const void* __restrict__ m2,
                                 const int* __restrict__ selfids) {
    int b = blockIdx.x;
    const int* nb; const int* rl; const void* m; bf16* oh; bf16* ol;
    if (b < BN_) { nb = nb1; rl = rl1; m = m1; oh = g_v1h; ol = g_v1l; }
    else         { b -= BN_; nb = nb2; rl = rl2; m = m2; oh = g_v2h; ol = g_v2l; }

    __shared__ int s_nb[KN_];
    __shared__ float s_rcnt[16];
    __shared__ int s_cnt;
    int t = threadIdx.x;
    if (t < 16) s_rcnt[t] = 0.f;
    __syncthreads();
    if (t < KN_) {   // warp 0
        int mk;
        if (g_mask_u8) mk = ((const unsigned char*)m)[b * KN_ + t];
        else           mk = ((const int*)m)[b * KN_ + t];
        mk = (mk != 0);
        int nbv = nb[b * KN_ + t];
        int rlv = rl[b * KN_ + t];
        unsigned bal = __ballot_sync(0xFFFFFFFFu, mk);
        if (mk) {
            int pos = __popc(bal & ((1u << t) - 1u));
            s_nb[pos] = nbv;
            atomicAdd(&s_rcnt[rlv], 1.f);
        }
        if (t == 0) s_cnt = __popc(bal);
    }
    __syncthreads();
    int cnt = s_cnt;
    int d = t;

    // relation contribution via counts (rel rows are hot in L1/L2)
    float acc = 0.f;
#pragma unroll
    for (int r = 0; r < NREL_; r++)
        acc = fmaf(s_rcnt[r], rel[r * DN_ + d], acc);

    // neighbor gather: 4 independent accumulators for MLP
    float a0 = 0.f, a1 = 0.f, a2 = 0.f, a3 = 0.f;
    int k = 0;
    for (; k + 3 < cnt; k += 4) {
        const float* p0 = nf + (size_t)s_nb[k + 0] * DN_ + d;
        const float* p1 = nf + (size_t)s_nb[k + 1] * DN_ + d;
        const float* p2 = nf + (size_t)s_nb[k + 2] * DN_ + d;
        const float* p3 = nf + (size_t)s_nb[k + 3] * DN_ + d;
        float v0 = *p0, v1 = *p1, v2 = *p2, v3 = *p3;
        a0 += v0; a1 += v1; a2 += v2; a3 += v3;
    }
    for (; k < cnt; k++)
        a0 += nf[(size_t)s_nb[k] * DN_ + d];
    acc += (a0 + a1) + (a2 + a3);

    float res;
    if (cnt > 0) res = acc / (float)cnt;
    else         res = nf[(size_t)selfids[b] * DN_ + d];
    split_store(&oh[(size_t)b * DN_ + d], &ol[(size_t)b * DN_ + d], res);
}

// ---------------- async-copy / ldmatrix / mma primitives ----------------
__device__ __forceinline__ void cp16(uint32_t s, const void* g) {
    asm volatile("cp.async.cg.shared.global [%0], [%1], 16;\n" :: "r"(s), "l"(g));
}
__device__ __forceinline__ void cpcommit() {
    asm volatile("cp.async.commit_group;\n" ::: "memory");
}
template <int N>
__device__ __forceinline__ void cpwait() {
    asm volatile("cp.async.wait_group %0;\n" :: "n"(N) : "memory");
}
__device__ __forceinline__ void ldsm4(unsigned r[4], uint32_t a) {
    asm volatile("ldmatrix.sync.aligned.m8n8.x4.shared.b16 {%0,%1,%2,%3}, [%4];\n"
                 : "=r"(r[0]), "=r"(r[1]), "=r"(r[2]), "=r"(r[3]) : "r"(a));
}
__device__ __forceinline__ void mma16816(float c[4], unsigned a0, unsigned a1, unsigned a2, unsigned a3,
                                         unsigned b0, unsigned b1) {
    asm volatile("mma.sync.aligned.m16n8k16.row.col.f32.bf16.bf16.f32 "
                 "{%0,%1,%2,%3}, {%4,%5,%6,%7}, {%8,%9}, {%0,%1,%2,%3};\n"
                 : "+f"(c[0]), "+f"(c[1]), "+f"(c[2]), "+f"(c[3])
                 : "r"(a0), "r"(a1), "r"(a2), "r"(a3), "r"(b0), "r"(b1));
}

template <int BM, int BN>
__device__ __forceinline__ void issue_stage(uint32_t sb,
        const bf16* Ah, const bf16* Al, const bf16* Bh, const bf16* Bl,
        int bm, int bn, int ld, int k0, int tid) {
#pragma unroll
    for (int idx = tid; idx < BM * 4; idx += 256) {
        int row = idx >> 2, seg = idx & 3;
        size_t go = (size_t)(bm + row) * ld + k0 + seg * 8;
        uint32_t so = (uint32_t)(row * TS + seg * 8) * 2;
        cp16(sb + so, Ah + go);
        cp16(sb + BM * TS * 2 + so, Al + go);
    }
#pragma unroll
    for (int idx = tid; idx < BN * 4; idx += 256) {
        int row = idx >> 2, seg = idx & 3;
        size_t go = (size_t)(bn + row) * ld + k0 + seg * 8;
        uint32_t so = (uint32_t)(row * TS + seg * 8) * 2;
        cp16(sb + BM * TS * 4 + so, Bh + go);
        cp16(sb + BM * TS * 4 + BN * TS * 2 + so, Bl + go);
    }
}

// 2-stage pipelined split-bf16 MMA mainloop (Ah*Bh + Ah*Bl + Al*Bh)
template <int BM, int BN, int MS, int NS, int WCOLS, int NIT>
__device__ __forceinline__ void mma_pipe(float (&c)[MS][NS][4],
        const bf16* Ah, const bf16* Al, const bf16* Bh, const bf16* Bl,
        int bm, int bn, int ld, char* smem_dyn, int tid) {
    constexpr int SSB = (BM + BN) * TS * 4;
    uint32_t sb0 = (uint32_t)__cvta_generic_to_shared(smem_dyn);
    int lane = tid & 31, w = tid >> 5;
    int wr = w / WCOLS, wc = w % WCOLS;
    int rowA = (lane & 7) + ((lane >> 3) & 1) * 8;
    int kA   = (lane >> 4) * 8;
    int rowB = (lane & 7) + (lane >> 4) * 8;
    int kB   = ((lane >> 3) & 1) * 8;

    issue_stage<BM, BN>(sb0, Ah, Al, Bh, Bl, bm, bn, ld, 0, tid);
    cpcommit();

#pragma unroll 1
    for (int it = 0; it < NIT; ++it) {
        uint32_t scur = sb0 + (it & 1) * SSB;
        if (it + 1 < NIT) {
            issue_stage<BM, BN>(sb0 + ((it + 1) & 1) * SSB, Ah, Al, Bh, Bl, bm, bn, ld, (it + 1) * 32, tid);
            cpcommit();
            cpwait<1>();
        } else {
            cpwait<0>();
        }
        __syncthreads();
        uint32_t sAh_ = scur;
        uint32_t sAl_ = scur + BM * TS * 2;
        uint32_t sBh_ = scur + BM * TS * 4;
        uint32_t sBl_ = sBh_ + BN * TS * 2;
#pragma unroll
        for (int kk = 0; kk < 32; kk += 16) {
            unsigned ah[MS][4];
#pragma unroll
            for (int ms = 0; ms < MS; ms++)
                ldsm4(ah[ms], sAh_ + (uint32_t)(((wr * MS + ms) * 16 + rowA) * TS + kk + kA) * 2);
            unsigned bh[NS][2];
#pragma unroll
            for (int np = 0; np < NS / 2; np++) {
                unsigned r[4];
                ldsm4(r, sBh_ + (uint32_t)((wc * NS * 8 + np * 16 + rowB) * TS + kk + kB) * 2);
                bh[2 * np][0] = r[0]; bh[2 * np][1] = r[1];
                bh[2 * np + 1][0] = r[2]; bh[2 * np + 1][1] = r[3];
            }
#pragma unroll
            for (int ms = 0; ms < MS; ms++)
#pragma unroll
                for (int ns = 0; ns < NS; ns++)
                    mma16816(c[ms][ns], ah[ms][0], ah[ms][1], ah[ms][2], ah[ms][3], bh[ns][0], bh[ns][1]);
            {
                unsigned bl[NS][2];
#pragma unroll
                for (int np = 0; np < NS / 2; np++) {
                    unsigned r[4];
                    ldsm4(r, sBl_ + (uint32_t)((wc * NS * 8 + np * 16 + rowB) * TS + kk + kB) * 2);
                    bl[2 * np][0] = r[0]; bl[2 * np][1] = r[1];
                    bl[2 * np + 1][0] = r[2]; bl[2 * np + 1][1] = r[3];
                }
#pragma unroll
                for (int ms = 0; ms < MS; ms++)
#pragma unroll
                    for (int ns = 0; ns < NS; ns++)
                        mma16816(c[ms][ns], ah[ms][0], ah[ms][1], ah[ms][2], ah[ms][3], bl[ns][0], bl[ns][1]);
            }
            {
                unsigned al[MS][4];
#pragma unroll
                for (int ms = 0; ms < MS; ms++)
                    ldsm4(al[ms], sAl_ + (uint32_t)(((wr * MS + ms) * 16 + rowA) * TS + kk + kA) * 2);
#pragma unroll
                for (int ms = 0; ms < MS; ms++)
#pragma unroll
                    for (int ns = 0; ns < NS; ns++)
                        mma16816(c[ms][ns], al[ms][0], al[ms][1], al[ms][2], al[ms][3], bh[ns][0], bh[ns][1]);
            }
        }
        __syncthreads();
    }
}

// ---------------- proj-a: 128x64 tiles, grid (32,4,2) ----------------
__global__ void __launch_bounds__(256, 2) mma_projA_kernel(
        const float* __restrict__ b1a, const float* __restrict__ b2a) {
    extern __shared__ char smem_dyn[];
    int tid = threadIdx.x;
    int lane = tid & 31, w = tid >> 5;
    int wr = w >> 1, wc = w & 1;
    int grp = lane >> 2, qp = (lane & 3) * 2;
    int bm = blockIdx.x * 128, bn = blockIdx.y * 64;
    int view = blockIdx.z;
    const bf16* Ah = view ? g_v2h : g_v1h;
    const bf16* Al = view ? g_v2l : g_v1l;
    const bf16* Bh = view ? g_w2ath : g_w1ath;
    const bf16* Bl = view ? g_w2atl : g_w1atl;
    const float* bias = view ? b2a : b1a;
    bf16* Ch = view ? g_h2h : g_h1h;
    bf16* Cl = view ? g_h2l : g_h1l;

    float c[2][4][4] = {};
    mma_pipe<128, 64, 2, 4, 2, 8>(c, Ah, Al, Bh, Bl, bm, bn, DN_, smem_dyn, tid);

#pragma unroll
    for (int ms = 0; ms < 2; ms++) {
#pragma unroll
        for (int ns = 0; ns < 4; ns++) {
            int col = bn + wc * 32 + ns * 8 + qp;
            float b0 = bias[col], b1 = bias[col + 1];
#pragma unroll
            for (int h = 0; h < 2; h++) {
                int row = bm + (wr * 2 + ms) * 16 + grp + 8 * h;
                float v0 = fmaxf(c[ms][ns][2 * h + 0] + b0, 0.f);
                float v1 = fmaxf(c[ms][ns][2 * h + 1] + b1, 0.f);
                bf16 h0 = __float2bfloat16(v0), h1 = __float2bfloat16(v1);
                bf16 l0 = __float2bfloat16(v0 - __bfloat162float(h0));
                bf16 l1 = __float2bfloat16(v1 - __bfloat162float(h1));
                __nv_bfloat162 hp; hp.x = h0; hp.y = h1;
                __nv_bfloat162 lp; lp.x = l0; lp.y = l1;
                *(__nv_bfloat162*)(Ch + (size_t)row * DN_ + col) = hp;
                *(__nv_bfloat162*)(Cl + (size_t)row * DN_ + col) = lp;
            }
        }
    }
}

// ---------------- proj-b: 64x128 tiles + fused L2-normalize + split, grid (64,1,2) ----------------
__global__ void __launch_bounds__(256, 2) mma_projB_kernel(
        const float* __restrict__ b1b, const float* __restrict__ b2b) {
    extern __shared__ char smem_dyn[];
    __shared__ float s_ss[64];
    int tid = threadIdx.x;
    int lane = tid & 31, w = tid >> 5;
    int wr = w >> 2, wc = w & 3;
    int grp = lane >> 2, qp = (lane & 3) * 2;
    int bm = blockIdx.x * 64;
    int view = blockIdx.z;
    const bf16* Ah = view ? g_h2h : g_h1h;
    const bf16* Al = view ? g_h2l : g_h1l;
    const bf16* Bh = view ? g_w2bth : g_w1bth;
    const bf16* Bl = view ? g_w2btl : g_w1btl;
    const float* bias = view ? b2b : b1b;
    bf16* Zh = view ? g_z2h : g_z1h;
    bf16* Zl = view ? g_z2l : g_z1l;

    if (tid < 64) s_ss[tid] = 0.f;

    float c[2][4][4] = {};
    mma_pipe<64, 128, 2, 4, 4, 8>(c, Ah, Al, Bh, Bl, bm, 0, DN_, smem_dyn, tid);

    float vv[2][4][4];
#pragma unroll
    for (int ms = 0; ms < 2; ms++) {
#pragma unroll
        for (int ns = 0; ns < 4; ns++) {
            int col = wc * 32 + ns * 8 + qp;
            float b0 = bias[col], b1 = bias[col + 1];
#pragma unroll
            for (int h = 0; h < 2; h++) {
                vv[ms][ns][2 * h + 0] = c[ms][ns][2 * h + 0] + b0;
                vv[ms][ns][2 * h + 1] = c[ms][ns][2 * h + 1] + b1;
            }
        }
    }
#pragma unroll
    for (int ms = 0; ms < 2; ms++)
#pragma unroll
        for (int h = 0; h < 2; h++) {
            float ss = 0.f;
#pragma unroll
            for (int ns = 0; ns < 4; ns++) {
                float a = vv[ms][ns][2 * h + 0], b = vv[ms][ns][2 * h + 1];
                ss = fmaf(a, a, ss); ss = fmaf(b, b, ss);
            }
            ss += __shfl_xor_sync(0xFFFFFFFFu, ss, 1);
            ss += __shfl_xor_sync(0xFFFFFFFFu, ss, 2);
            if ((lane & 3) == 0)
                atomicAdd(&s_ss[(wr * 2 + ms) * 16 + grp + 8 * h], ss);
        }
    __syncthreads();

#pragma unroll
    for (int ms = 0; ms < 2; ms++) {
#pragma unroll
        for (int h = 0; h < 2; h++) {
            int rloc = (wr * 2 + ms) * 16 + grp + 8 * h;
            float rinv = rsqrtf(s_ss[rloc]);
            int row = bm + rloc;
#pragma unroll
            for (int ns = 0; ns < 4; ns++) {
                int col = wc * 32 + ns * 8 + qp;
                float v0 = vv[ms][ns][2 * h + 0] * rinv;
                float v1 = vv[ms][ns][2 * h + 1] * rinv;
                bf16 h0 = __float2bfloat16(v0), h1 = __float2bfloat16(v1);
                bf16 l0 = __float2bfloat16(v0 - __bfloat162float(h0));
                bf16 l1 = __float2bfloat16(v1 - __bfloat162float(h1));
                __nv_bfloat162 hp; hp.x = h0; hp.y = h1;
                __nv_bfloat162 lp; lp.x = l0; lp.y = l1;
                *(__nv_bfloat162*)(Zh + (size_t)row * DH_ + col) = hp;
                *(__nv_bfloat162*)(Zl + (size_t)row * DH_ + col) = lp;
            }
        }
    }
}

// ---------------- sim GEMM + shifted-exp LSE: 128x128 tiles, grid (32,32) ----------------
__global__ void __launch_bounds__(256, 2) sim_lse_kernel() {
    extern __shared__ char smem_dyn[];
    __shared__ float s_rs[128], s_cs[128];
    int tid = threadIdx.x;
    int lane = tid & 31, w = tid >> 5;
    int wr = w >> 2, wc = w & 3;
    int grp = lane >> 2, qp = (lane & 3) * 2;
    int bm = blockIdx.x * 128, bn = blockIdx.y * 128;
    if (tid < 128) { s_rs[tid] = 0.f; s_cs[tid] = 0.f; }

    float c[4][4][4] = {};
    mma_pipe<128, 128, 4, 4, 4, 4>(c, g_z1h, g_z1l, g_z2h, g_z2l, bm, bn, DH_, smem_dyn, tid);

    float rs[4][2] = {}, cs[4][2] = {};
#pragma unroll
    for (int ms = 0; ms < 4; ms++) {
#pragma unroll
        for (int ns = 0; ns < 4; ns++) {
#pragma unroll
            for (int r = 0; r < 4; r++) {
                int h = r >> 1, p = r & 1;
                int row = bm + (wr * 4 + ms) * 16 + grp + 8 * h;
                int col = bn + wc * 32 + ns * 8 + qp + p;
                float s = c[ms][ns][r] * INV_T;
                if (row == col) g_diag[row] = s;
                float ev = __expf(s - INV_T);
                rs[ms][h] += ev;
                cs[ns][p] += ev;
            }
        }
    }
#pragma unroll
    for (int ms = 0; ms < 4; ms++)
#pragma unroll
        for (int h = 0; h < 2; h++) {
            float v = rs[ms][h];
            v += __shfl_xor_sync(0xFFFFFFFFu, v, 1);
            v += __shfl_xor_sync(0xFFFFFFFFu, v, 2);
            if ((lane & 3) == 0)
                atomicAdd(&s_rs[(wr * 4 + ms) * 16 + grp + 8 * h], v);
        }
#pragma unroll
    for (int ns = 0; ns < 4; ns++)
#pragma unroll
        for (int p = 0; p < 2; p++) {
            float v = cs[ns][p];
            v += __shfl_xor_sync(0xFFFFFFFFu, v, 4);
            v += __shfl_xor_sync(0xFFFFFFFFu, v, 8);
            v += __shfl_xor_sync(0xFFFFFFFFu, v, 16);
            if (grp == 0)
                atomicAdd(&s_cs[wc * 32 + ns * 8 + qp + p], v);
        }
    __syncthreads();
    if (tid < 128) {
        atomicAdd(&g_rowsum[bm + tid], s_rs[tid]);
        atomicAdd(&g_colsum[bn + tid], s_cs[tid]);
    }
}

// ---------------- final loss reduce ----------------
__global__ void loss_kernel(float* __restrict__ out) {
    float acc = 0.f;
    for (int i = threadIdx.x; i < BN_; i += 256) {
        acc += 0.5f * (logf(g_rowsum[i]) + logf(g_colsum[i])) + INV_T - g_diag[i];
    }
#pragma unroll
    for (int off = 16; off; off >>= 1) acc += __shfl_xor_sync(0xFFFFFFFFu, acc, off);
    __shared__ float wsum[8];
    if ((threadIdx.x & 31) == 0) wsum[threadIdx.x >> 5] = acc;
    __syncthreads();
    if (threadIdx.x == 0) {
        float tot = 0.f;
        for (int k = 0; k < 8; k++) tot += wsum[k];
        out[0] = tot / (float)BN_;
    }
}

// ---------------- launch ----------------
extern "C" void kernel_launch(void* const* d_in, const int* in_sizes, int n_in,
                              void* d_out, int out_size) {
    const float* nf   = (const float*)d_in[0];
    const float* rel  = (const float*)d_in[1];
    const int*   nb1  = (const int*)d_in[2];
    const int*   rl1  = (const int*)d_in[3];
    const void*  m1   = d_in[4];
    const int*   nb2  = (const int*)d_in[5];
    const int*   rl2  = (const int*)d_in[6];
    const void*  m2   = d_in[7];
    const int*   self_ = (const int*)d_in[8];
    const float* W1a  = (const float*)d_in[9];
    const float* b1a  = (const float*)d_in[10];
    const float* W1b  = (const float*)d_in[11];
    const float* b1b  = (const float*)d_in[12];
    const float* W2a  = (const float*)d_in[13];
    const float* b2a  = (const float*)d_in[14];
    const float* W2b  = (const float*)d_in[15];
    const float* b2b  = (const float*)d_in[16];

    const int smemA  = (128 + 64) * TS * 4 * 2;   // 61440
    const int smemB  = (64 + 128) * TS * 4 * 2;   // 61440
    const int smemS  = (128 + 128) * TS * 4 * 2;  // 81920
    cudaFuncSetAttribute(mma_projA_kernel, cudaFuncAttributeMaxDynamicSharedMemorySize, smemA);
    cudaFuncSetAttribute(mma_projB_kernel, cudaFuncAttributeMaxDynamicSharedMemorySize, smemB);
    cudaFuncSetAttribute(sim_lse_kernel,   cudaFuncAttributeMaxDynamicSharedMemorySize, smemS);

    prep_kernel<<<48, 256>>>(W1a, W1b, W2a, W2b, (const unsigned int*)m1);
    aggregate_kernel<<<2 * BN_, 256>>>(nf, rel, nb1, rl1, m1, nb2, rl2, m2, self_);
    mma_projA_kernel<<<dim3(32, 4, 2), 256, smemA>>>(b1a, b2a);
    mma_projB_kernel<<<dim3(64, 1, 2), 256, smemB>>>(b1b, b2b);
    sim_lse_kernel<<<dim3(32, 32), 256, smemS>>>();
    loss_kernel<<<1, 256>>>((float*)d_out);
}

// round 11
// speedup vs baseline: 2.7067x; 1.2534x over previous
#include <cuda_runtime.h>
#include <cuda_bf16.h>
#include <math.h>
#include <stdint.h>

#define BN_ 4096
#define KN_ 32
#define DN_ 256
#define DH_ 128
#define NREL_ 9
#define INV_T 14.285714285714286f
#define TS 40    // smem tile stride (32 + 8 pad)
#define TSK 136  // full-K smem stride (128 + 8 pad)

typedef __nv_bfloat16 bf16;

// ---------------- scratch ----------------
__device__ __align__(16) bf16 g_v1h[BN_ * DN_];
__device__ __align__(16) bf16 g_v1l[BN_ * DN_];
__device__ __align__(16) bf16 g_v2h[BN_ * DN_];
__device__ __align__(16) bf16 g_v2l[BN_ * DN_];
__device__ __align__(16) bf16 g_h1h[BN_ * DN_];
__device__ __align__(16) bf16 g_h1l[BN_ * DN_];
__device__ __align__(16) bf16 g_h2h[BN_ * DN_];
__device__ __align__(16) bf16 g_h2l[BN_ * DN_];
__device__ __align__(16) bf16 g_z1h[BN_ * DH_];
__device__ __align__(16) bf16 g_z2h[BN_ * DH_];
__device__ __align__(16) bf16 g_w1ath[DN_ * DN_];
__device__ __align__(16) bf16 g_w1atl[DN_ * DN_];
__device__ __align__(16) bf16 g_w1bth[DH_ * DN_];
__device__ __align__(16) bf16 g_w1btl[DH_ * DN_];
__device__ __align__(16) bf16 g_w2ath[DN_ * DN_];
__device__ __align__(16) bf16 g_w2atl[DN_ * DN_];
__device__ __align__(16) bf16 g_w2bth[DH_ * DN_];
__device__ __align__(16) bf16 g_w2btl[DH_ * DN_];
__device__ float g_rowsum[BN_];
__device__ float g_colsum[BN_];
__device__ float g_diag[BN_];
__device__ int   g_mask_u8;

__device__ __forceinline__ void split_store(bf16* ph, bf16* pl, float v) {
    bf16 h = __float2bfloat16(v);
    *ph = h;
    *pl = __float2bfloat16(v - __bfloat162float(h));
}

// ---------------- prep: mask detect + zero + tiled weight split/transpose ----------------
__global__ void prep_kernel(const float* __restrict__ W1a, const float* __restrict__ W1b,
                            const float* __restrict__ W2a, const float* __restrict__ W2b,
                            const unsigned int* __restrict__ m1) {
    int blk = blockIdx.x;
    int t = threadIdx.x;

    int zi = blk * 256 + t;
    if (zi < BN_) { g_rowsum[zi] = 0.f; g_colsum[zi] = 0.f; }

    __shared__ int sf;
    if (t == 0) sf = 0;
    __syncthreads();
    if (blk == 0) {
        int f = 0;
        for (int i = t; i < 4096; i += 256)
            if (m1[i] > 1u) f = 1;
        if (f) sf = 1;
    }
    __syncthreads();
    if (blk == 0 && t == 0) g_mask_u8 = sf;

    const float* W; bf16* Th; bf16* Tl; int N, tile;
    const int K = DN_;
    if (blk < 16)      { W = W1a; Th = g_w1ath; Tl = g_w1atl; N = 256; tile = blk; }
    else if (blk < 24) { W = W1b; Th = g_w1bth; Tl = g_w1btl; N = 128; tile = blk - 16; }
    else if (blk < 40) { W = W2a; Th = g_w2ath; Tl = g_w2atl; N = 256; tile = blk - 24; }
    else               { W = W2b; Th = g_w2bth; Tl = g_w2btl; N = 128; tile = blk - 40; }
    int tn = N / 64;
    int k0 = (tile / tn) * 64, n0 = (tile % tn) * 64;

    __shared__ float s[64][65];
#pragma unroll
    for (int i = 0; i < 16; i++) {
        int idx = t + i * 256;
        int r = idx >> 6, c = idx & 63;
        s[r][c] = W[(size_t)(k0 + r) * N + n0 + c];
    }
    __syncthreads();
#pragma unroll
    for (int i = 0; i < 16; i++) {
        int idx = t + i * 256;
        int n = idx >> 6, k = idx & 63;
        split_store(&Th[(size_t)(n0 + n) * K + k0 + k],
                    &Tl[(size_t)(n0 + n) * K + k0 + k], s[k][n]);
    }
}

// ---------------- aggregation: float4 row gather, 4 neighbor-groups ----------------
__global__ void aggregate_kernel(const float* __restrict__ nf,
                                 const float* __restrict__ rel,
                                 const int* __restrict__ nb1, const int* __restrict__ rl1, const void* __restrict__ m1,
                                 const int* __restrict__ nb2, const int* __restrict__ rl2, const void* __restrict__ m2,
                                 const int* __restrict__ selfids) {
    int b = blockIdx.x;
    const int* nb; const int* rl; const void* m; bf16* oh; bf16* ol;
    if (b < BN_) { nb = nb1; rl = rl1; m = m1; oh = g_v1h; ol = g_v1l; }
    else         { b -= BN_; nb = nb2; rl = rl2; m = m2; oh = g_v2h; ol = g_v2l; }

    __shared__ int s_nb[KN_];
    __shared__ float s_rcnt[16];
    __shared__ int s_cnt;
    __shared__ __align__(16) float s_part[4 * 256];
    int t = threadIdx.x;
    if (t < 16) s_rcnt[t] = 0.f;
    __syncthreads();
    if (t < KN_) {   // warp 0: mask decode + index compaction + relation counts
        int mk;
        if (g_mask_u8) mk = ((const unsigned char*)m)[b * KN_ + t];
        else           mk = ((const int*)m)[b * KN_ + t];
        mk = (mk != 0);
        int nbv = nb[b * KN_ + t];
        int rlv = rl[b * KN_ + t];
        unsigned bal = __ballot_sync(0xFFFFFFFFu, mk);
        if (mk) {
            int pos = __popc(bal & ((1u << t) - 1u));
            s_nb[pos] = nbv;
            atomicAdd(&s_rcnt[rlv], 1.f);
        }
        if (t == 0) s_cnt = __popc(bal);
    }
    __syncthreads();
    int cnt = s_cnt;

    // gather: group g handles neighbors k ≡ g (mod 4); 64 threads cover a 1KB row in float4
    int g = t >> 6, l64 = t & 63;
    float4 a0 = make_float4(0.f, 0.f, 0.f, 0.f);
    float4 a1 = make_float4(0.f, 0.f, 0.f, 0.f);
    int k = g;
    for (; k + 4 < cnt; k += 8) {
        float4 v0 = *((const float4*)(nf + (size_t)s_nb[k] * DN_) + l64);
        float4 v1 = *((const float4*)(nf + (size_t)s_nb[k + 4] * DN_) + l64);
        a0.x += v0.x; a0.y += v0.y; a0.z += v0.z; a0.w += v0.w;
        a1.x += v1.x; a1.y += v1.y; a1.z += v1.z; a1.w += v1.w;
    }
    if (k < cnt) {
        float4 v0 = *((const float4*)(nf + (size_t)s_nb[k] * DN_) + l64);
        a0.x += v0.x; a0.y += v0.y; a0.z += v0.z; a0.w += v0.w;
    }
    a0.x += a1.x; a0.y += a1.y; a0.z += a1.z; a0.w += a1.w;
    ((float4*)s_part)[g * 64 + l64] = a0;
    __syncthreads();

    // finalize: thread t owns dim t
    int d = t;
    float acc = s_part[d] + s_part[256 + d] + s_part[512 + d] + s_part[768 + d];
#pragma unroll
    for (int r = 0; r < NREL_; r++)
        acc = fmaf(s_rcnt[r], rel[r * DN_ + d], acc);
    float res;
    if (cnt > 0) res = acc / (float)cnt;
    else         res = nf[(size_t)selfids[b] * DN_ + d];
    split_store(&oh[(size_t)b * DN_ + d], &ol[(size_t)b * DN_ + d], res);
}

// ---------------- async-copy / ldmatrix / mma primitives ----------------
__device__ __forceinline__ void cp16(uint32_t s, const void* g) {
    asm volatile("cp.async.cg.shared.global [%0], [%1], 16;\n" :: "r"(s), "l"(g));
}
__device__ __forceinline__ void cpcommit() {
    asm volatile("cp.async.commit_group;\n" ::: "memory");
}
template <int N>
__device__ __forceinline__ void cpwait() {
    asm volatile("cp.async.wait_group %0;\n" :: "n"(N) : "memory");
}
__device__ __forceinline__ void ldsm4(unsigned r[4], uint32_t a) {
    asm volatile("ldmatrix.sync.aligned.m8n8.x4.shared.b16 {%0,%1,%2,%3}, [%4];\n"
                 : "=r"(r[0]), "=r"(r[1]), "=r"(r[2]), "=r"(r[3]) : "r"(a));
}
__device__ __forceinline__ void mma16816(float c[4], unsigned a0, unsigned a1, unsigned a2, unsigned a3,
                                         unsigned b0, unsigned b1) {
    asm volatile("mma.sync.aligned.m16n8k16.row.col.f32.bf16.bf16.f32 "
                 "{%0,%1,%2,%3}, {%4,%5,%6,%7}, {%8,%9}, {%0,%1,%2,%3};\n"
                 : "+f"(c[0]), "+f"(c[1]), "+f"(c[2]), "+f"(c[3])
                 : "r"(a0), "r"(a1), "r"(a2), "r"(a3), "r"(b0), "r"(b1));
}

template <int BM, int BN>
__device__ __forceinline__ void issue_stage(uint32_t sb,
        const bf16* Ah, const bf16* Al, const bf16* Bh, const bf16* Bl,
        int bm, int bn, int ld, int k0, int tid) {
#pragma unroll
    for (int idx = tid; idx < BM * 4; idx += 256) {
        int row = idx >> 2, seg = idx & 3;
        size_t go = (size_t)(bm + row) * ld + k0 + seg * 8;
        uint32_t so = (uint32_t)(row * TS + seg * 8) * 2;
        cp16(sb + so, Ah + go);
        cp16(sb + BM * TS * 2 + so, Al + go);
    }
#pragma unroll
    for (int idx = tid; idx < BN * 4; idx += 256) {
        int row = idx >> 2, seg = idx & 3;
        size_t go = (size_t)(bn + row) * ld + k0 + seg * 8;
        uint32_t so = (uint32_t)(row * TS + seg * 8) * 2;
        cp16(sb + BM * TS * 4 + so, Bh + go);
        cp16(sb + BM * TS * 4 + BN * TS * 2 + so, Bl + go);
    }
}

// 2-stage pipelined split-bf16 MMA mainloop (Ah*Bh + Ah*Bl + Al*Bh)
template <int BM, int BN, int MS, int NS, int WCOLS, int NIT>
__device__ __forceinline__ void mma_pipe(float (&c)[MS][NS][4],
        const bf16* Ah, const bf16* Al, const bf16* Bh, const bf16* Bl,
        int bm, int bn, int ld, char* smem_dyn, int tid) {
    constexpr int SSB = (BM + BN) * TS * 4;
    uint32_t sb0 = (uint32_t)__cvta_generic_to_shared(smem_dyn);
    int lane = tid & 31, w = tid >> 5;
    int wr = w / WCOLS, wc = w % WCOLS;
    int rowA = (lane & 7) + ((lane >> 3) & 1) * 8;
    int kA   = (lane >> 4) * 8;
    int rowB = (lane & 7) + (lane >> 4) * 8;
    int kB   = ((lane >> 3) & 1) * 8;

    issue_stage<BM, BN>(sb0, Ah, Al, Bh, Bl, bm, bn, ld, 0, tid);
    cpcommit();

#pragma unroll 1
    for (int it = 0; it < NIT; ++it) {
        uint32_t scur = sb0 + (it & 1) * SSB;
        if (it + 1 < NIT) {
            issue_stage<BM, BN>(sb0 + ((it + 1) & 1) * SSB, Ah, Al, Bh, Bl, bm, bn, ld, (it + 1) * 32, tid);
            cpcommit();
            cpwait<1>();
        } else {
            cpwait<0>();
        }
        __syncthreads();
        uint32_t sAh_ = scur;
        uint32_t sAl_ = scur + BM * TS * 2;
        uint32_t sBh_ = scur + BM * TS * 4;
        uint32_t sBl_ = sBh_ + BN * TS * 2;
#pragma unroll
        for (int kk = 0; kk < 32; kk += 16) {
            unsigned ah[MS][4];
#pragma unroll
            for (int ms = 0; ms < MS; ms++)
                ldsm4(ah[ms], sAh_ + (uint32_t)(((wr * MS + ms) * 16 + rowA) * TS + kk + kA) * 2);
            unsigned bh[NS][2];
#pragma unroll
            for (int np = 0; np < NS / 2; np++) {
                unsigned r[4];
                ldsm4(r, sBh_ + (uint32_t)((wc * NS * 8 + np * 16 + rowB) * TS + kk + kB) * 2);
                bh[2 * np][0] = r[0]; bh[2 * np][1] = r[1];
                bh[2 * np + 1][0] = r[2]; bh[2 * np + 1][1] = r[3];
            }
#pragma unroll
            for (int ms = 0; ms < MS; ms++)
#pragma unroll
                for (int ns = 0; ns < NS; ns++)
                    mma16816(c[ms][ns], ah[ms][0], ah[ms][1], ah[ms][2], ah[ms][3], bh[ns][0], bh[ns][1]);
            {
                unsigned bl[NS][2];
#pragma unroll
                for (int np = 0; np < NS / 2; np++) {
                    unsigned r[4];
                    ldsm4(r, sBl_ + (uint32_t)((wc * NS * 8 + np * 16 + rowB) * TS + kk + kB) * 2);
                    bl[2 * np][0] = r[0]; bl[2 * np][1] = r[1];
                    bl[2 * np + 1][0] = r[2]; bl[2 * np + 1][1] = r[3];
                }
#pragma unroll
                for (int ms = 0; ms < MS; ms++)
#pragma unroll
                    for (int ns = 0; ns < NS; ns++)
                        mma16816(c[ms][ns], ah[ms][0], ah[ms][1], ah[ms][2], ah[ms][3], bl[ns][0], bl[ns][1]);
            }
            {
                unsigned al[MS][4];
#pragma unroll
                for (int ms = 0; ms < MS; ms++)
                    ldsm4(al[ms], sAl_ + (uint32_t)(((wr * MS + ms) * 16 + rowA) * TS + kk + kA) * 2);
#pragma unroll
                for (int ms = 0; ms < MS; ms++)
#pragma unroll
                    for (int ns = 0; ns < NS; ns++)
                        mma16816(c[ms][ns], al[ms][0], al[ms][1], al[ms][2], al[ms][3], bh[ns][0], bh[ns][1]);
            }
        }
        __syncthreads();
    }
}

// ---------------- proj-a: 128x64 tiles, grid (32,4,2) ----------------
__global__ void __launch_bounds__(256, 2) mma_projA_kernel(
        const float* __restrict__ b1a, const float* __restrict__ b2a) {
    extern __shared__ char smem_dyn[];
    int tid = threadIdx.x;
    int lane = tid & 31, w = tid >> 5;
    int wr = w >> 1, wc = w & 1;
    int grp = lane >> 2, qp = (lane & 3) * 2;
    int bm = blockIdx.x * 128, bn = blockIdx.y * 64;
    int view = blockIdx.z;
    const bf16* Ah = view ? g_v2h : g_v1h;
    const bf16* Al = view ? g_v2l : g_v1l;
    const bf16* Bh = view ? g_w2ath : g_w1ath;
    const bf16* Bl = view ? g_w2atl : g_w1atl;
    const float* bias = view ? b2a : b1a;
    bf16* Ch = view ? g_h2h : g_h1h;
    bf16* Cl = view ? g_h2l : g_h1l;

    float c[2][4][4] = {};
    mma_pipe<128, 64, 2, 4, 2, 8>(c, Ah, Al, Bh, Bl, bm, bn, DN_, smem_dyn, tid);

#pragma unroll
    for (int ms = 0; ms < 2; ms++) {
#pragma unroll
        for (int ns = 0; ns < 4; ns++) {
            int col = bn + wc * 32 + ns * 8 + qp;
            float b0 = bias[col], b1 = bias[col + 1];
#pragma unroll
            for (int h = 0; h < 2; h++) {
                int row = bm + (wr * 2 + ms) * 16 + grp + 8 * h;
                float v0 = fmaxf(c[ms][ns][2 * h + 0] + b0, 0.f);
                float v1 = fmaxf(c[ms][ns][2 * h + 1] + b1, 0.f);
                bf16 h0 = __float2bfloat16(v0), h1 = __float2bfloat16(v1);
                bf16 l0 = __float2bfloat16(v0 - __bfloat162float(h0));
                bf16 l1 = __float2bfloat16(v1 - __bfloat162float(h1));
                __nv_bfloat162 hp; hp.x = h0; hp.y = h1;
                __nv_bfloat162 lp; lp.x = l0; lp.y = l1;
                *(__nv_bfloat162*)(Ch + (size_t)row * DN_ + col) = hp;
                *(__nv_bfloat162*)(Cl + (size_t)row * DN_ + col) = lp;
            }
        }
    }
}

// ---------------- proj-b: 32x128 tiles + fused L2-normalize, grid (128,1,2) ----------------
__global__ void __launch_bounds__(256, 2) mma_projB_kernel(
        const float* __restrict__ b1b, const float* __restrict__ b2b) {
    extern __shared__ char smem_dyn[];
    __shared__ float s_ss[32];
    int tid = threadIdx.x;
    int lane = tid & 31, w = tid >> 5;
    int wr = w >> 2, wc = w & 3;
    int grp = lane >> 2, qp = (lane & 3) * 2;
    int bm = blockIdx.x * 32;
    int view = blockIdx.z;
    const bf16* Ah = view ? g_h2h : g_h1h;
    const bf16* Al = view ? g_h2l : g_h1l;
    const bf16* Bh = view ? g_w2bth : g_w1bth;
    const bf16* Bl = view ? g_w2btl : g_w1btl;
    const float* bias = view ? b2b : b1b;
    bf16* Zh = view ? g_z2h : g_z1h;

    if (tid < 32) s_ss[tid] = 0.f;

    float c[1][4][4] = {};
    mma_pipe<32, 128, 1, 4, 4, 8>(c, Ah, Al, Bh, Bl, bm, 0, DN_, smem_dyn, tid);

    float vv[4][4];
#pragma unroll
    for (int ns = 0; ns < 4; ns++) {
        int col = wc * 32 + ns * 8 + qp;
        float b0 = bias[col], b1 = bias[col + 1];
#pragma unroll
        for (int h = 0; h < 2; h++) {
            vv[ns][2 * h + 0] = c[0][ns][2 * h + 0] + b0;
            vv[ns][2 * h + 1] = c[0][ns][2 * h + 1] + b1;
        }
    }
#pragma unroll
    for (int h = 0; h < 2; h++) {
        float ss = 0.f;
#pragma unroll
        for (int ns = 0; ns < 4; ns++) {
            float a = vv[ns][2 * h + 0], b = vv[ns][2 * h + 1];
            ss = fmaf(a, a, ss); ss = fmaf(b, b, ss);
        }
        ss += __shfl_xor_sync(0xFFFFFFFFu, ss, 1);
        ss += __shfl_xor_sync(0xFFFFFFFFu, ss, 2);
        if ((lane & 3) == 0)
            atomicAdd(&s_ss[wr * 16 + grp + 8 * h], ss);
    }
    __syncthreads();

#pragma unroll
    for (int h = 0; h < 2; h++) {
        int rloc = wr * 16 + grp + 8 * h;
        float rinv = rsqrtf(s_ss[rloc]);
        int row = bm + rloc;
#pragma unroll
        for (int ns = 0; ns < 4; ns++) {
            int col = wc * 32 + ns * 8 + qp;
            float v0 = vv[ns][2 * h + 0] * rinv;
            float v1 = vv[ns][2 * h + 1] * rinv;
            __nv_bfloat162 hp;
            hp.x = __float2bfloat16(v0); hp.y = __float2bfloat16(v1);
            *(__nv_bfloat162*)(Zh + (size_t)row * DH_ + col) = hp;
        }
    }
}

// ---------------- sim: pure-bf16 single-stage GEMM + shifted-exp LSE, grid (32,32) ----------------
__global__ void __launch_bounds__(256, 2) sim_lse_kernel() {
    extern __shared__ char smem_dyn[];
    __shared__ float s_rs[128], s_cs[128];
    int tid = threadIdx.x;
    int lane = tid & 31, w = tid >> 5;
    int wr = w >> 2, wc = w & 3;
    int grp = lane >> 2, qp = (lane & 3) * 2;
    int bm = blockIdx.x * 128, bn = blockIdx.y * 128;
    if (tid < 128) { s_rs[tid] = 0.f; s_cs[tid] = 0.f; }

    uint32_t sA = (uint32_t)__cvta_generic_to_shared(smem_dyn);
    uint32_t sB = sA + 128 * TSK * 2;

    // load full 128x128 bf16 tiles of z1h / z2h (one stage, whole K)
#pragma unroll
    for (int i = 0; i < 8; i++) {
        int idx = tid + i * 256;
        int row = idx >> 4, seg = idx & 15;
        uint32_t so = (uint32_t)(row * TSK + seg * 8) * 2;
        cp16(sA + so, g_z1h + (size_t)(bm + row) * DH_ + seg * 8);
        cp16(sB + so, g_z2h + (size_t)(bn + row) * DH_ + seg * 8);
    }
    cpcommit();
    cpwait<0>();
    __syncthreads();

    int rowA = (lane & 7) + ((lane >> 3) & 1) * 8;
    int kA   = (lane >> 4) * 8;
    int rowB = (lane & 7) + (lane >> 4) * 8;
    int kB   = ((lane >> 3) & 1) * 8;

    float c[4][4][4] = {};
#pragma unroll
    for (int kk = 0; kk < 128; kk += 16) {
        unsigned a[4][4];
#pragma unroll
        for (int ms = 0; ms < 4; ms++)
            ldsm4(a[ms], sA + (uint32_t)(((wr * 4 + ms) * 16 + rowA) * TSK + kk + kA) * 2);
        unsigned bfr[4][2];
#pragma unroll
        for (int np = 0; np < 2; np++) {
            unsigned r[4];
            ldsm4(r, sB + (uint32_t)((wc * 32 + np * 16 + rowB) * TSK + kk + kB) * 2);
            bfr[2 * np][0] = r[0]; bfr[2 * np][1] = r[1];
            bfr[2 * np + 1][0] = r[2]; bfr[2 * np + 1][1] = r[3];
        }
#pragma unroll
        for (int ms = 0; ms < 4; ms++)
#pragma unroll
            for (int ns = 0; ns < 4; ns++)
                mma16816(c[ms][ns], a[ms][0], a[ms][1], a[ms][2], a[ms][3], bfr[ns][0], bfr[ns][1]);
    }

    float rs[4][2] = {}, cs[4][2] = {};
#pragma unroll
    for (int ms = 0; ms < 4; ms++) {
#pragma unroll
        for (int ns = 0; ns < 4; ns++) {
#pragma unroll
            for (int r = 0; r < 4; r++) {
                int h = r >> 1, p = r & 1;
                int row = bm + (wr * 4 + ms) * 16 + grp + 8 * h;
                int col = bn + wc * 32 + ns * 8 + qp + p;
                float s = c[ms][ns][r] * INV_T;
                if (row == col) g_diag[row] = s;
                float ev = __expf(s - INV_T);
                rs[ms][h] += ev;
                cs[ns][p] += ev;
            }
        }
    }
#pragma unroll
    for (int ms = 0; ms < 4; ms++)
#pragma unroll
        for (int h = 0; h < 2; h++) {
            float v = rs[ms][h];
            v += __shfl_xor_sync(0xFFFFFFFFu, v, 1);
            v += __shfl_xor_sync(0xFFFFFFFFu, v, 2);
            if ((lane & 3) == 0)
                atomicAdd(&s_rs[(wr * 4 + ms) * 16 + grp + 8 * h], v);
        }
#pragma unroll
    for (int ns = 0; ns < 4; ns++)
#pragma unroll
        for (int p = 0; p < 2; p++) {
            float v = cs[ns][p];
            v += __shfl_xor_sync(0xFFFFFFFFu, v, 4);
            v += __shfl_xor_sync(0xFFFFFFFFu, v, 8);
            v += __shfl_xor_sync(0xFFFFFFFFu, v, 16);
            if (grp == 0)
                atomicAdd(&s_cs[wc * 32 + ns * 8 + qp + p], v);
        }
    __syncthreads();
    if (tid < 128) {
        atomicAdd(&g_rowsum[bm + tid], s_rs[tid]);
        atomicAdd(&g_colsum[bn + tid], s_cs[tid]);
    }
}

// ---------------- final loss reduce ----------------
__global__ void loss_kernel(float* __restrict__ out) {
    float acc = 0.f;
    for (int i = threadIdx.x; i < BN_; i += 256) {
        acc += 0.5f * (logf(g_rowsum[i]) + logf(g_colsum[i])) + INV_T - g_diag[i];
    }
#pragma unroll
    for (int off = 16; off; off >>= 1) acc += __shfl_xor_sync(0xFFFFFFFFu, acc, off);
    __shared__ float wsum[8];
    if ((threadIdx.x & 31) == 0) wsum[threadIdx.x >> 5] = acc;
    __syncthreads();
    if (threadIdx.x == 0) {
        float tot = 0.f;
        for (int k = 0; k < 8; k++) tot += wsum[k];
        out[0] = tot / (float)BN_;
    }
}

// ---------------- launch ----------------
extern "C" void kernel_launch(void* const* d_in, const int* in_sizes, int n_in,
                              void* d_out, int out_size) {
    const float* nf   = (const float*)d_in[0];
    const float* rel  = (const float*)d_in[1];
    const int*   nb1  = (const int*)d_in[2];
    const int*   rl1  = (const int*)d_in[3];
    const void*  m1   = d_in[4];
    const int*   nb2  = (const int*)d_in[5];
    const int*   rl2  = (const int*)d_in[6];
    const void*  m2   = d_in[7];
    const int*   self_ = (const int*)d_in[8];
    const float* W1a  = (const float*)d_in[9];
    const float* b1a  = (const float*)d_in[10];
    const float* W1b  = (const float*)d_in[11];
    const float* b1b  = (const float*)d_in[12];
    const float* W2a  = (const float*)d_in[13];
    const float* b2a  = (const float*)d_in[14];
    const float* W2b  = (const float*)d_in[15];
    const float* b2b  = (const float*)d_in[16];

    const int smemA  = (128 + 64) * TS * 4 * 2;   // 61440
    const int smemB  = (32 + 128) * TS * 4 * 2;   // 51200
    const int smemS  = 2 * 128 * TSK * 2;         // 69632
    cudaFuncSetAttribute(mma_projA_kernel, cudaFuncAttributeMaxDynamicSharedMemorySize, smemA);
    cudaFuncSetAttribute(mma_projB_kernel, cudaFuncAttributeMaxDynamicSharedMemorySize, smemB);
    cudaFuncSetAttribute(sim_lse_kernel,   cudaFuncAttributeMaxDynamicSharedMemorySize, smemS);

    prep_kernel<<<48, 256>>>(W1a, W1b, W2a, W2b, (const unsigned int*)m1);
    aggregate_kernel<<<2 * BN_, 256>>>(nf, rel, nb1, rl1, m1, nb2, rl2, m2, self_);
    mma_projA_kernel<<<dim3(32, 4, 2), 256, smemA>>>(b1a, b2a);
    mma_projB_kernel<<<dim3(128, 1, 2), 256, smemB>>>(b1b, b2b);
    sim_lse_kernel<<<dim3(32, 32), 256, smemS>>>();
    loss_kernel<<<1, 256>>>((float*)d_out);
}